// round 1
// baseline (speedup 1.0000x reference)
#include <cuda_runtime.h>
#include <cuda_bf16.h>

// ---------------- problem constants ----------------
#define NA     50000
#define MPAD   50048            // 391 * 128
#define NEIGH  12
#define NEDGE  (NA * NEIGH)
#define MAXDEG 64
#define HID    128

// ---------------- scratch (static device globals; no allocation) ----------------
__device__ float g_exp [(size_t)MPAD * 1440];   // expanded features (bond reuses prefix)
__device__ float g_proj[(size_t)MPAD * 256];    // [proj_l | proj_r]
__device__ float g_bo  [(size_t)MPAD * HID];
__device__ float g_ao  [(size_t)MPAD * HID];
__device__ int   g_cnt [NA];
__device__ int   g_inc [(size_t)NA * MAXDEG];   // ELL incoming-edge source lists

// ---------------- graph inversion ----------------
__global__ void zero_cnt_kernel() {
    int i = blockIdx.x * blockDim.x + threadIdx.x;
    if (i < NA) g_cnt[i] = 0;
}

__global__ void count_kernel(const int* __restrict__ nbr) {
    int e = blockIdx.x * blockDim.x + threadIdx.x;
    if (e >= NEDGE) return;
    int d = nbr[e];
    int p = atomicAdd(&g_cnt[d], 1);
    if (p < MAXDEG) g_inc[(size_t)d * MAXDEG + p] = e / NEIGH;  // src atom
}

// ---------------- Gaussian basis expansion ----------------
// out[n*(nper*steps) + p*steps + s] = exp(-(fea[n,p] - (mu0 + s*dmu))^2 * inv_g2)
__global__ void expand_kernel(const float* __restrict__ fea, int nper, int steps,
                              float mu0, float dmu, float inv_g2, long total) {
    long idx = (long)blockIdx.x * blockDim.x + threadIdx.x;
    if (idx >= total) return;
    int  s  = (int)(idx % steps);
    long np = idx / steps;
    long n  = np / nper;
    float v = 0.f;
    if (n < NA) {
        float a = fea[np];
        float d = a - (mu0 + (float)s * dmu);
        v = __expf(-d * d * inv_g2);
    }
    g_exp[idx] = v;
}

// ---------------- fp32 SIMT GEMM:  g_proj[M,256] = A[M,K] @ [Wl;Wr]^T ----------------
// A selected by asel: 0 = g_exp, 1 = g_bo, 2 = g_ao. Wl/Wr are [128,K] row-major.
// blockIdx.y == 0 -> cols 0..127 use Wl ; blockIdx.y == 1 -> cols 128..255 use Wr.
__global__ void __launch_bounds__(256, 2)
gemm_kernel(int asel, const float* __restrict__ Wl, const float* __restrict__ Wr, int K) {
    const float* A = (asel == 0) ? g_exp : (asel == 1 ? g_bo : g_ao);
    const float* W = blockIdx.y ? Wr : Wl;

    __shared__ float As[16][132];
    __shared__ float Bs[16][132];

    const int tid  = threadIdx.x;
    const int tr   = tid >> 4;          // 0..15 : row micro-tile
    const int tc   = tid & 15;          // 0..15 : col micro-tile
    const int lrow = tid >> 2;          // 0..63 : loader row
    const int lk   = (tid & 3) << 2;    // 0,4,8,12 : loader k-offset

    const size_t rowbase = (size_t)blockIdx.x * 128;
    const float* Ap0 = A + (rowbase + lrow)      * (size_t)K + lk;
    const float* Ap1 = A + (rowbase + lrow + 64) * (size_t)K + lk;
    const float* Wp0 = W + (size_t)lrow        * K + lk;
    const float* Wp1 = W + (size_t)(lrow + 64) * K + lk;

    float acc[8][8];
#pragma unroll
    for (int i = 0; i < 8; i++)
#pragma unroll
        for (int j = 0; j < 8; j++) acc[i][j] = 0.f;

    for (int kt = 0; kt < K; kt += 16) {
        float4 a0 = *(const float4*)(Ap0 + kt);
        float4 a1 = *(const float4*)(Ap1 + kt);
        float4 b0 = *(const float4*)(Wp0 + kt);
        float4 b1 = *(const float4*)(Wp1 + kt);
        __syncthreads();
        As[lk+0][lrow]    = a0.x; As[lk+1][lrow]    = a0.y; As[lk+2][lrow]    = a0.z; As[lk+3][lrow]    = a0.w;
        As[lk+0][lrow+64] = a1.x; As[lk+1][lrow+64] = a1.y; As[lk+2][lrow+64] = a1.z; As[lk+3][lrow+64] = a1.w;
        Bs[lk+0][lrow]    = b0.x; Bs[lk+1][lrow]    = b0.y; Bs[lk+2][lrow]    = b0.z; Bs[lk+3][lrow]    = b0.w;
        Bs[lk+0][lrow+64] = b1.x; Bs[lk+1][lrow+64] = b1.y; Bs[lk+2][lrow+64] = b1.z; Bs[lk+3][lrow+64] = b1.w;
        __syncthreads();
#pragma unroll
        for (int k = 0; k < 16; k++) {
            float ar[8], br[8];
            *(float4*)&ar[0] = *(const float4*)&As[k][tr * 8];
            *(float4*)&ar[4] = *(const float4*)&As[k][tr * 8 + 4];
            *(float4*)&br[0] = *(const float4*)&Bs[k][tc * 8];
            *(float4*)&br[4] = *(const float4*)&Bs[k][tc * 8 + 4];
#pragma unroll
            for (int i = 0; i < 8; i++)
#pragma unroll
                for (int j = 0; j < 8; j++)
                    acc[i][j] = fmaf(ar[i], br[j], acc[i][j]);
        }
    }

    const size_t crow = rowbase + (size_t)tr * 8;
    const int    ccol = blockIdx.y * 128 + tc * 8;
#pragma unroll
    for (int i = 0; i < 8; i++) {
        *(float4*)&g_proj[(crow + i) * 256 + ccol]     = make_float4(acc[i][0], acc[i][1], acc[i][2], acc[i][3]);
        *(float4*)&g_proj[(crow + i) * 256 + ccol + 4] = make_float4(acc[i][4], acc[i][5], acc[i][6], acc[i][7]);
    }
}

// ---------------- mean-aggregate (gather) + bias + lin_r + ReLU ----------------
// one warp per destination atom; lane owns features [lane*4, lane*4+4)
__global__ void gather_kernel(const float* __restrict__ bias, int osel) {
    int gw   = (blockIdx.x * blockDim.x + threadIdx.x) >> 5;
    int lane = threadIdx.x & 31;
    if (gw >= NA) return;

    int deg = g_cnt[gw];
    int dcl = min(deg, MAXDEG);
    int src_l = (lane < dcl) ? g_inc[(size_t)gw * MAXDEG + lane] : 0;

    float4 acc = make_float4(0.f, 0.f, 0.f, 0.f);
    for (int p = 0; p < dcl; p++) {
        int src = (p < 32) ? __shfl_sync(0xffffffffu, src_l, p)
                           : g_inc[(size_t)gw * MAXDEG + p];
        float4 h = *(const float4*)(g_proj + (size_t)src * 256 + lane * 4);
        acc.x += h.x; acc.y += h.y; acc.z += h.z; acc.w += h.w;
    }
    float inv = 1.f / (float)max(deg, 1);
    float4 pr = *(const float4*)(g_proj + (size_t)gw * 256 + 128 + lane * 4);
    float4 bb = *(const float4*)(bias + lane * 4);
    float4 o;
    o.x = fmaxf(fmaf(acc.x, inv, bb.x + pr.x), 0.f);
    o.y = fmaxf(fmaf(acc.y, inv, bb.y + pr.y), 0.f);
    o.z = fmaxf(fmaf(acc.z, inv, bb.z + pr.z), 0.f);
    o.w = fmaxf(fmaf(acc.w, inv, bb.w + pr.w), 0.f);
    float* out = osel ? g_ao : g_bo;
    *(float4*)(out + (size_t)gw * HID + lane * 4) = o;
}

// ---------------- crystal mean-pool + linear head ----------------
__global__ void pool_kernel(const int* __restrict__ crys,
                            const float* __restrict__ Wfc, const float* __restrict__ bfc,
                            float* __restrict__ out) {
    int b = blockIdx.x;       // 500 crystals
    int f = threadIdx.x;      // 256 features
    int start = crys[b * 2], end = crys[b * 2 + 1];
    const float* src = (f < 128) ? g_bo : g_ao;
    int fo = (f < 128) ? f : (f - 128);
    float s = 0.f;
    for (int a = start; a < end; a++) s += src[(size_t)a * HID + fo];
    __shared__ float pooled[256];
    pooled[f] = s / (float)(end - start);
    __syncthreads();
    int wid = f >> 5, lane = f & 31;
    if (wid < 2) {
        float d = 0.f;
        for (int i = lane; i < 256; i += 32) d += pooled[i] * Wfc[wid * 256 + i];
#pragma unroll
        for (int off = 16; off; off >>= 1) d += __shfl_down_sync(0xffffffffu, d, off);
        if (lane == 0) out[b * 2 + wid] = d + bfc[wid];
    }
}

// ---------------- host launcher ----------------
extern "C" void kernel_launch(void* const* d_in, const int* in_sizes, int n_in,
                              void* d_out, int out_size) {
    if (n_in < 19) return;

    int I_bond, I_angle, I_W1b, I_b1b, I_W1br, I_W1a, I_b1a, I_W1ar,
        I_W2b, I_b2b, I_W2br, I_W2a, I_b2a, I_W2ar, I_Wfc, I_bfc, I_nbr, I_crys;

    if (in_sizes[0] == 600000 && in_sizes[2] == 50000) {
        // setup_inputs dict order: bond, angle, species, nbr, crys, W1b,b1b,W1br,W1a,b1a,W1ar,...
        I_bond = 0; I_angle = 1; I_nbr = 3; I_crys = 4;
        I_W1b = 5;  I_b1b = 6;  I_W1br = 7;  I_W1a = 8;  I_b1a = 9;  I_W1ar = 10;
        I_W2b = 11; I_b2b = 12; I_W2br = 13; I_W2a = 14; I_b2a = 15; I_W2ar = 16;
        I_Wfc = 17; I_bfc = 18;
    } else if (in_sizes[0] == 600000) {
        // reference signature order
        I_bond = 0; I_angle = 1; I_W1b = 2; I_b1b = 3; I_W1br = 4;
        I_W1a = 5;  I_b1a = 6;  I_W1ar = 7; I_W2b = 8; I_b2b = 9; I_W2br = 10;
        I_W2a = 11; I_b2a = 12; I_W2ar = 13; I_Wfc = 14; I_bfc = 15;
        I_nbr = 17; I_crys = 18;
    } else {
        // ASCII-sorted fallback: W1a,W1ar,W1b,W1br,W2a,W2ar,W2b,W2br,Wfc,angle,b1a,b1b,b2a,b2b,bfc,bond,crys,nbr,species
        I_W1a = 0; I_W1ar = 1; I_W1b = 2; I_W1br = 3;
        I_W2a = 4; I_W2ar = 5; I_W2b = 6; I_W2br = 7; I_Wfc = 8;
        I_angle = 9; I_b1a = 10; I_b1b = 11; I_b2a = 12; I_b2b = 13; I_bfc = 14;
        I_bond = 15; I_crys = 16; I_nbr = 17;
    }

    const float* bond  = (const float*)d_in[I_bond];
    const float* angle = (const float*)d_in[I_angle];
    const int*   nbr   = (const int*)  d_in[I_nbr];
    const int*   crys  = (const int*)  d_in[I_crys];
    const float* W1b   = (const float*)d_in[I_W1b];
    const float* b1b   = (const float*)d_in[I_b1b];
    const float* W1br  = (const float*)d_in[I_W1br];
    const float* W1a   = (const float*)d_in[I_W1a];
    const float* b1a   = (const float*)d_in[I_b1a];
    const float* W1ar  = (const float*)d_in[I_W1ar];
    const float* W2b   = (const float*)d_in[I_W2b];
    const float* b2b   = (const float*)d_in[I_b2b];
    const float* W2br  = (const float*)d_in[I_W2br];
    const float* W2a   = (const float*)d_in[I_W2a];
    const float* b2a   = (const float*)d_in[I_b2a];
    const float* W2ar  = (const float*)d_in[I_W2ar];
    const float* Wfc   = (const float*)d_in[I_Wfc];
    const float* bfc   = (const float*)d_in[I_bfc];
    float* out = (float*)d_out;

    const dim3 ggemm(MPAD / 128, 2);
    const int gatherBlocks = (NA * 32 + 255) / 256;

    // graph inversion (shared across all 4 convs)
    zero_cnt_kernel<<<(NA + 255) / 256, 256>>>();
    count_kernel<<<(NEDGE + 255) / 256, 256>>>(nbr);

    // ---- layer 1, bond path: [N,480] ----
    {
        long total = (long)MPAD * 480;
        expand_kernel<<<(unsigned)((total + 255) / 256), 256>>>(bond, 12, 40, 0.f, 8.f / 39.f, 25.f, total);
    }
    gemm_kernel<<<ggemm, 256>>>(0, W1b, W1br, 480);
    gather_kernel<<<gatherBlocks, 256>>>(b1b, 0);

    // ---- layer 1, angle path: [N,1440] ----
    {
        long total = (long)MPAD * 1440;
        expand_kernel<<<(unsigned)((total + 255) / 256), 256>>>(angle, 144, 10, -1.f, 2.f / 9.f, 25.f, total);
    }
    gemm_kernel<<<ggemm, 256>>>(0, W1a, W1ar, 1440);
    gather_kernel<<<gatherBlocks, 256>>>(b1a, 1);

    // ---- layer 2, bond path ----
    gemm_kernel<<<ggemm, 256>>>(1, W2b, W2br, 128);
    gather_kernel<<<gatherBlocks, 256>>>(b2b, 0);

    // ---- layer 2, angle path ----
    gemm_kernel<<<ggemm, 256>>>(2, W2a, W2ar, 128);
    gather_kernel<<<gatherBlocks, 256>>>(b2a, 1);

    // ---- pool + head ----
    pool_kernel<<<500, 256>>>(crys, Wfc, bfc, out);
}

// round 3
// speedup vs baseline: 1.3951x; 1.3951x over previous
#include <cuda_runtime.h>
#include <cstdint>
#include <mma.h>

using namespace nvcuda;

// ---------------- problem constants ----------------
#define NA     50000
#define MPAD   50048            // 391 * 128
#define NEIGH  12
#define NEDGE  (NA * NEIGH)
#define MAXDEG 64
#define HID    128

// ---------------- scratch (static device globals; no allocation) ----------------
__device__ float g_exp [(size_t)MPAD * 1440];   // expanded features (bond reuses prefix)
__device__ float g_proj[(size_t)MPAD * 256];    // [proj_l | proj_r]
__device__ float g_bo  [(size_t)MPAD * HID];
__device__ float g_ao  [(size_t)MPAD * HID];
__device__ int   g_cnt [NA];
__device__ int   g_inc [(size_t)NA * MAXDEG];   // ELL incoming-edge source lists

// ---------------- graph inversion ----------------
__global__ void zero_cnt_kernel() {
    int i = blockIdx.x * blockDim.x + threadIdx.x;
    if (i < NA) g_cnt[i] = 0;
}
__global__ void count_kernel(const int* __restrict__ nbr) {
    int e = blockIdx.x * blockDim.x + threadIdx.x;
    if (e >= NEDGE) return;
    int d = nbr[e];
    int p = atomicAdd(&g_cnt[d], 1);
    if (p < MAXDEG) g_inc[(size_t)d * MAXDEG + p] = e / NEIGH;
}

// ---------------- Gaussian basis expansion ----------------
__global__ void expand_kernel(const float* __restrict__ fea, int nper, int steps,
                              float mu0, float dmu, float inv_g2, long total) {
    long idx = (long)blockIdx.x * blockDim.x + threadIdx.x;
    if (idx >= total) return;
    int  s  = (int)(idx % steps);
    long np = idx / steps;
    long n  = np / nper;
    float v = 0.f;
    if (n < NA) {
        float a = fea[np];
        float d = a - (mu0 + (float)s * dmu);
        v = __expf(-d * d * inv_g2);
    }
    g_exp[idx] = v;
}

// ---------------- cp.async helpers ----------------
__device__ __forceinline__ uint32_t smem_u32(const void* p) {
    uint32_t a;
    asm("{ .reg .u64 t; cvta.to.shared.u64 t, %1; cvt.u32.u64 %0, t; }" : "=r"(a) : "l"(p));
    return a;
}
#define CP_ASYNC16(dst, src) \
    asm volatile("cp.async.cg.shared.global [%0], [%1], 16;" :: "r"(dst), "l"(src))
#define CP_COMMIT()  asm volatile("cp.async.commit_group;" ::: "memory")
#define CP_WAIT(n)   asm volatile("cp.async.wait_group %0;" :: "n"(n) : "memory")

// ---------------- wmma tf32 GEMM: g_proj[M, y*128..] = A[M,K] @ W^T ----------------
// block tile 128(m) x 128(n), K-chunk 32, double-buffered smem, 8 warps (4m x 2n),
// warp tile 32(m) x 64(n) -> 2x4 m16n16k8 fragments.
#define SM_STRIDE 36
#define SM_ABUF   (128 * SM_STRIDE * 4)   // 18432 bytes per buffer
#define SM_TOTAL  (4 * SM_ABUF)           // A0,A1,B0,B1 = 73728 bytes

__global__ void __launch_bounds__(256, 2)
wmma_gemm_kernel(int asel, const float* __restrict__ Wl, const float* __restrict__ Wr, int K)
{
    extern __shared__ float sm[];
    float* const smA[2] = { sm,                  sm + 128 * SM_STRIDE };
    float* const smB[2] = { sm + 2 * 128 * SM_STRIDE, sm + 3 * 128 * SM_STRIDE };

    const float* __restrict__ A = (asel == 0) ? g_exp : (asel == 1 ? g_bo : g_ao);
    const float* __restrict__ W = blockIdx.y ? Wr : Wl;

    const int tid  = threadIdx.x;
    const int row8 = tid >> 3;         // 0..31 loader row base (steps of +32 via i)
    const int c4   = (tid & 7) << 2;   // 0,4,...,28

    const size_t rowbase = (size_t)blockIdx.x * 128;
    const int T = K >> 5;

    // per-thread global src pointers (row = row8 + i*32)
    const float* aSrc = A + (rowbase + row8) * (size_t)K + c4;
    const float* bSrc = W + (size_t)row8 * K + c4;
    const uint32_t aDst = smem_u32(smA[0]) + (row8 * SM_STRIDE + c4) * 4;
    const uint32_t bDst = smem_u32(smB[0]) + (row8 * SM_STRIDE + c4) * 4;
    const uint32_t bufStep = SM_ABUF;                  // bytes between buf 0 and 1
    const size_t   rowStepA = 32 * (size_t)K;          // +32 rows
    const uint32_t rowStepS = 32 * SM_STRIDE * 4;

    // prefetch chunk 0
#pragma unroll
    for (int i = 0; i < 4; i++) {
        CP_ASYNC16(aDst + i * rowStepS, aSrc + i * rowStepA);
        CP_ASYNC16(bDst + i * rowStepS, bSrc + i * rowStepA);
    }
    CP_COMMIT();

    const int warp = tid >> 5;
    const int wm = warp >> 1;          // 0..3
    const int wn = warp & 1;           // 0..1

    wmma::fragment<wmma::accumulator, 16, 16, 8, float> acc[2][4];
#pragma unroll
    for (int i = 0; i < 2; i++)
#pragma unroll
        for (int j = 0; j < 4; j++) wmma::fill_fragment(acc[i][j], 0.f);

    for (int t = 0; t < T; t++) {
        const int b = t & 1;
        if (t + 1 < T) {
            const int nb = (t + 1) & 1;
            const int k0 = (t + 1) << 5;
#pragma unroll
            for (int i = 0; i < 4; i++) {
                CP_ASYNC16(aDst + nb * bufStep + i * rowStepS, aSrc + k0 + i * rowStepA);
                CP_ASYNC16(bDst + nb * bufStep + i * rowStepS, bSrc + k0 + i * rowStepA);
            }
            CP_COMMIT();
            CP_WAIT(1);
        } else {
            CP_WAIT(0);
        }
        __syncthreads();

        const float* As = smA[b];
        const float* Bs = smB[b];
#pragma unroll
        for (int ks = 0; ks < 4; ks++) {
            wmma::fragment<wmma::matrix_a, 16, 16, 8, wmma::precision::tf32, wmma::row_major> af[2];
            wmma::fragment<wmma::matrix_b, 16, 16, 8, wmma::precision::tf32, wmma::col_major> bf[4];
#pragma unroll
            for (int mt = 0; mt < 2; mt++) {
                wmma::load_matrix_sync(af[mt], As + (wm * 32 + mt * 16) * SM_STRIDE + ks * 8, SM_STRIDE);
#pragma unroll
                for (int e = 0; e < af[mt].num_elements; e++)
                    af[mt].x[e] = wmma::__float_to_tf32(af[mt].x[e]);
            }
#pragma unroll
            for (int nt = 0; nt < 4; nt++) {
                wmma::load_matrix_sync(bf[nt], Bs + (wn * 64 + nt * 16) * SM_STRIDE + ks * 8, SM_STRIDE);
#pragma unroll
                for (int e = 0; e < bf[nt].num_elements; e++)
                    bf[nt].x[e] = wmma::__float_to_tf32(bf[nt].x[e]);
            }
#pragma unroll
            for (int mt = 0; mt < 2; mt++)
#pragma unroll
                for (int nt = 0; nt < 4; nt++)
                    wmma::mma_sync(acc[mt][nt], af[mt], bf[nt], acc[mt][nt]);
        }
        __syncthreads();
    }

    // epilogue: direct store to g_proj
    const int colbase = blockIdx.y * 128 + wn * 64;
#pragma unroll
    for (int mt = 0; mt < 2; mt++) {
        const size_t row = rowbase + wm * 32 + mt * 16;
#pragma unroll
        for (int nt = 0; nt < 4; nt++)
            wmma::store_matrix_sync(g_proj + row * 256 + colbase + nt * 16,
                                    acc[mt][nt], 256, wmma::mem_row_major);
    }
}

// ---------------- mean-aggregate (gather) + bias + lin_r + ReLU ----------------
__global__ void gather_kernel(const float* __restrict__ bias, int osel) {
    int gw   = (blockIdx.x * blockDim.x + threadIdx.x) >> 5;
    int lane = threadIdx.x & 31;
    if (gw >= NA) return;

    int deg = g_cnt[gw];
    int dcl = min(deg, MAXDEG);
    int src_l = (lane < dcl) ? g_inc[(size_t)gw * MAXDEG + lane] : 0;

    float4 acc = make_float4(0.f, 0.f, 0.f, 0.f);
    for (int p = 0; p < dcl; p++) {
        int src = (p < 32) ? __shfl_sync(0xffffffffu, src_l, p)
                           : g_inc[(size_t)gw * MAXDEG + p];
        float4 h = *(const float4*)(g_proj + (size_t)src * 256 + lane * 4);
        acc.x += h.x; acc.y += h.y; acc.z += h.z; acc.w += h.w;
    }
    float inv = 1.f / (float)max(deg, 1);
    float4 pr = *(const float4*)(g_proj + (size_t)gw * 256 + 128 + lane * 4);
    float4 bb = *(const float4*)(bias + lane * 4);
    float4 o;
    o.x = fmaxf(fmaf(acc.x, inv, bb.x + pr.x), 0.f);
    o.y = fmaxf(fmaf(acc.y, inv, bb.y + pr.y), 0.f);
    o.z = fmaxf(fmaf(acc.z, inv, bb.z + pr.z), 0.f);
    o.w = fmaxf(fmaf(acc.w, inv, bb.w + pr.w), 0.f);
    float* out = osel ? g_ao : g_bo;
    *(float4*)(out + (size_t)gw * HID + lane * 4) = o;
}

// ---------------- crystal mean-pool + linear head ----------------
__global__ void pool_kernel(const int* __restrict__ crys,
                            const float* __restrict__ Wfc, const float* __restrict__ bfc,
                            float* __restrict__ out) {
    int b = blockIdx.x;
    int f = threadIdx.x;
    int start = crys[b * 2], end = crys[b * 2 + 1];
    const float* src = (f < 128) ? g_bo : g_ao;
    int fo = (f < 128) ? f : (f - 128);
    float s = 0.f;
    for (int a = start; a < end; a++) s += src[(size_t)a * HID + fo];
    __shared__ float pooled[256];
    pooled[f] = s / (float)(end - start);
    __syncthreads();
    int wid = f >> 5, lane = f & 31;
    if (wid < 2) {
        float d = 0.f;
        for (int i = lane; i < 256; i += 32) d += pooled[i] * Wfc[wid * 256 + i];
#pragma unroll
        for (int off = 16; off; off >>= 1) d += __shfl_down_sync(0xffffffffu, d, off);
        if (lane == 0) out[b * 2 + wid] = d + bfc[wid];
    }
}

// ---------------- host launcher ----------------
extern "C" void kernel_launch(void* const* d_in, const int* in_sizes, int n_in,
                              void* d_out, int out_size) {
    if (n_in < 19) return;

    int I_bond, I_angle, I_W1b, I_b1b, I_W1br, I_W1a, I_b1a, I_W1ar,
        I_W2b, I_b2b, I_W2br, I_W2a, I_b2a, I_W2ar, I_Wfc, I_bfc, I_nbr, I_crys;

    if (in_sizes[0] == 600000 && in_sizes[2] == 50000) {
        I_bond = 0; I_angle = 1; I_nbr = 3; I_crys = 4;
        I_W1b = 5;  I_b1b = 6;  I_W1br = 7;  I_W1a = 8;  I_b1a = 9;  I_W1ar = 10;
        I_W2b = 11; I_b2b = 12; I_W2br = 13; I_W2a = 14; I_b2a = 15; I_W2ar = 16;
        I_Wfc = 17; I_bfc = 18;
    } else if (in_sizes[0] == 600000) {
        I_bond = 0; I_angle = 1; I_W1b = 2; I_b1b = 3; I_W1br = 4;
        I_W1a = 5;  I_b1a = 6;  I_W1ar = 7; I_W2b = 8; I_b2b = 9; I_W2br = 10;
        I_W2a = 11; I_b2a = 12; I_W2ar = 13; I_Wfc = 14; I_bfc = 15;
        I_nbr = 17; I_crys = 18;
    } else {
        I_W1a = 0; I_W1ar = 1; I_W1b = 2; I_W1br = 3;
        I_W2a = 4; I_W2ar = 5; I_W2b = 6; I_W2br = 7; I_Wfc = 8;
        I_angle = 9; I_b1a = 10; I_b1b = 11; I_b2a = 12; I_b2b = 13; I_bfc = 14;
        I_bond = 15; I_crys = 16; I_nbr = 17;
    }

    const float* bond  = (const float*)d_in[I_bond];
    const float* angle = (const float*)d_in[I_angle];
    const int*   nbr   = (const int*)  d_in[I_nbr];
    const int*   crys  = (const int*)  d_in[I_crys];
    const float* W1b   = (const float*)d_in[I_W1b];
    const float* b1b   = (const float*)d_in[I_b1b];
    const float* W1br  = (const float*)d_in[I_W1br];
    const float* W1a   = (const float*)d_in[I_W1a];
    const float* b1a   = (const float*)d_in[I_b1a];
    const float* W1ar  = (const float*)d_in[I_W1ar];
    const float* W2b   = (const float*)d_in[I_W2b];
    const float* b2b   = (const float*)d_in[I_b2b];
    const float* W2br  = (const float*)d_in[I_W2br];
    const float* W2a   = (const float*)d_in[I_W2a];
    const float* b2a   = (const float*)d_in[I_b2a];
    const float* W2ar  = (const float*)d_in[I_W2ar];
    const float* Wfc   = (const float*)d_in[I_Wfc];
    const float* bfc   = (const float*)d_in[I_bfc];
    float* out = (float*)d_out;

    cudaFuncSetAttribute(wmma_gemm_kernel, cudaFuncAttributeMaxDynamicSharedMemorySize, SM_TOTAL);

    const int gatherBlocks = (NA * 32 + 255) / 256;
    const dim3 ggemm(MPAD / 128, 2);

    zero_cnt_kernel<<<(NA + 255) / 256, 256>>>();
    count_kernel<<<(NEDGE + 255) / 256, 256>>>(nbr);

    // ---- layer 1, bond path: K=480 ----
    {
        long total = (long)MPAD * 480;
        expand_kernel<<<(unsigned)((total + 255) / 256), 256>>>(bond, 12, 40, 0.f, 8.f / 39.f, 25.f, total);
    }
    wmma_gemm_kernel<<<ggemm, 256, SM_TOTAL>>>(0, W1b, W1br, 480);
    gather_kernel<<<gatherBlocks, 256>>>(b1b, 0);

    // ---- layer 1, angle path: K=1440 ----
    {
        long total = (long)MPAD * 1440;
        expand_kernel<<<(unsigned)((total + 255) / 256), 256>>>(angle, 144, 10, -1.f, 2.f / 9.f, 25.f, total);
    }
    wmma_gemm_kernel<<<ggemm, 256, SM_TOTAL>>>(0, W1a, W1ar, 1440);
    gather_kernel<<<gatherBlocks, 256>>>(b1a, 1);

    // ---- layer 2, bond path: K=128 ----
    wmma_gemm_kernel<<<ggemm, 256, SM_TOTAL>>>(1, W2b, W2br, 128);
    gather_kernel<<<gatherBlocks, 256>>>(b2b, 0);

    // ---- layer 2, angle path: K=128 ----
    wmma_gemm_kernel<<<ggemm, 256, SM_TOTAL>>>(2, W2a, W2ar, 128);
    gather_kernel<<<gatherBlocks, 256>>>(b2a, 1);

    // ---- pool + head ----
    pool_kernel<<<500, 256>>>(crys, Wfc, bfc, out);
}

// round 6
// speedup vs baseline: 1.4802x; 1.0610x over previous
#include <cuda_runtime.h>
#include <cstdint>
#include <mma.h>

using namespace nvcuda;

// ---------------- problem constants ----------------
#define NA     50000
#define MPAD   50048            // 391 * 128
#define NEIGH  12
#define NEDGE  (NA * NEIGH)
#define MAXDEG 64
#define HID    128

// ---------------- scratch (static device globals; no allocation) ----------------
__device__ float g_exp [(size_t)MPAD * 1440];   // expanded features (bond reuses prefix)
__device__ float g_proj[(size_t)MPAD * 256];    // [proj_l | proj_r]
__device__ float g_bo  [(size_t)MPAD * HID];
__device__ float g_ao  [(size_t)MPAD * HID];
__device__ int   g_cnt [NA];
__device__ int   g_inc [(size_t)NA * MAXDEG];   // ELL incoming-edge source lists

// ---------------- graph inversion ----------------
__global__ void zero_cnt_kernel() {
    int i = blockIdx.x * blockDim.x + threadIdx.x;
    if (i < NA) g_cnt[i] = 0;
}
__global__ void count_kernel(const int* __restrict__ nbr) {
    int e = blockIdx.x * blockDim.x + threadIdx.x;
    if (e >= NEDGE) return;
    int d = nbr[e];
    int p = atomicAdd(&g_cnt[d], 1);
    if (p < MAXDEG) g_inc[(size_t)d * MAXDEG + p] = e / NEIGH;
}

// ---------------- full-range exp on FMA/ALU pipes (for x <= 0) ----------------
__device__ __forceinline__ float fast_exp(float x) {
    float t = x * 1.4426950408889634f;                 // x * log2(e)
    int   n = __float2int_rn(t);
    float r = (t - (float)n) * 0.6931471805599453f;    // r in [-0.347, 0.347]
    float p = fmaf(r, 1.f/720.f, 1.f/120.f);           // degree-6 Taylor of e^r
    p = fmaf(p, r, 1.f/24.f);
    p = fmaf(p, r, 1.f/6.f);
    p = fmaf(p, r, 0.5f);
    p = fmaf(p, r, 1.f);
    p = fmaf(p, r, 1.f);
    int e = n + 127;
    float s = __int_as_float(max(e, 0) << 23);         // 2^n, flush to 0 below 2^-127
    return p * s;
}

// ---------------- Gaussian basis expansion (identical structure to round-3 pass) ----------------
// out[n*(NPER*STEPS) + p*STEPS + s] = exp(-(fea[n,p] - (mu0 + s*dmu))^2 * inv_g2)
template<int STEPS, int NPER>
__global__ void expand_kernel(const float* __restrict__ fea,
                              float mu0, float dmu, float inv_g2, long total) {
    long idx = (long)blockIdx.x * blockDim.x + threadIdx.x;
    if (idx >= total) return;
    int  s  = (int)(idx % STEPS);
    long np = idx / STEPS;
    long n  = np / NPER;
    float v = 0.f;
    if (n < NA) {
        float a = fea[np];
        float d = a - fmaf((float)s, dmu, mu0);
        v = fast_exp(-d * d * inv_g2);
    }
    g_exp[idx] = v;
}

// ---------------- cp.async helpers ----------------
__device__ __forceinline__ uint32_t smem_u32(const void* p) {
    uint32_t a;
    asm("{ .reg .u64 t; cvta.to.shared.u64 t, %1; cvt.u32.u64 %0, t; }" : "=r"(a) : "l"(p));
    return a;
}
#define CP_ASYNC16(dst, src) \
    asm volatile("cp.async.cg.shared.global [%0], [%1], 16;" :: "r"(dst), "l"(src))
#define CP_COMMIT()  asm volatile("cp.async.commit_group;" ::: "memory")
#define CP_WAIT(n)   asm volatile("cp.async.wait_group %0;" :: "n"(n) : "memory")

// ---------------- wmma tf32 GEMM: g_proj[M, y*128..] = A[M,K] @ W^T ----------------
// block tile 128(m) x 128(n), K-chunk 32, double-buffered smem, 8 warps (4m x 2n),
// warp tile 32(m) x 64(n) -> 2x4 m16n16k8 fragments.
#define SM_STRIDE 36
#define SM_ABUF   (128 * SM_STRIDE * 4)   // 18432 bytes per buffer
#define SM_TOTAL  (4 * SM_ABUF)           // A0,A1,B0,B1 = 73728 bytes

__global__ void __launch_bounds__(256, 2)
wmma_gemm_kernel(int asel, const float* __restrict__ Wl, const float* __restrict__ Wr, int K)
{
    extern __shared__ float sm[];
    float* const smA[2] = { sm,                  sm + 128 * SM_STRIDE };
    float* const smB[2] = { sm + 2 * 128 * SM_STRIDE, sm + 3 * 128 * SM_STRIDE };

    const float* __restrict__ A = (asel == 0) ? g_exp : (asel == 1 ? g_bo : g_ao);
    const float* __restrict__ W = blockIdx.y ? Wr : Wl;

    const int tid  = threadIdx.x;
    const int row8 = tid >> 3;         // 0..31 loader row base (steps of +32 via i)
    const int c4   = (tid & 7) << 2;   // 0,4,...,28

    const size_t rowbase = (size_t)blockIdx.x * 128;
    const int T = K >> 5;

    const float* aSrc = A + (rowbase + row8) * (size_t)K + c4;
    const float* bSrc = W + (size_t)row8 * K + c4;
    const uint32_t aDst = smem_u32(smA[0]) + (row8 * SM_STRIDE + c4) * 4;
    const uint32_t bDst = smem_u32(smB[0]) + (row8 * SM_STRIDE + c4) * 4;
    const uint32_t bufStep = SM_ABUF;
    const size_t   rowStepA = 32 * (size_t)K;
    const uint32_t rowStepS = 32 * SM_STRIDE * 4;

#pragma unroll
    for (int i = 0; i < 4; i++) {
        CP_ASYNC16(aDst + i * rowStepS, aSrc + i * rowStepA);
        CP_ASYNC16(bDst + i * rowStepS, bSrc + i * rowStepA);
    }
    CP_COMMIT();

    const int warp = tid >> 5;
    const int wm = warp >> 1;
    const int wn = warp & 1;

    wmma::fragment<wmma::accumulator, 16, 16, 8, float> acc[2][4];
#pragma unroll
    for (int i = 0; i < 2; i++)
#pragma unroll
        for (int j = 0; j < 4; j++) wmma::fill_fragment(acc[i][j], 0.f);

    for (int t = 0; t < T; t++) {
        const int b = t & 1;
        if (t + 1 < T) {
            const int nb = (t + 1) & 1;
            const int k0 = (t + 1) << 5;
#pragma unroll
            for (int i = 0; i < 4; i++) {
                CP_ASYNC16(aDst + nb * bufStep + i * rowStepS, aSrc + k0 + i * rowStepA);
                CP_ASYNC16(bDst + nb * bufStep + i * rowStepS, bSrc + k0 + i * rowStepA);
            }
            CP_COMMIT();
            CP_WAIT(1);
        } else {
            CP_WAIT(0);
        }
        __syncthreads();

        const float* As = smA[b];
        const float* Bs = smB[b];
#pragma unroll
        for (int ks = 0; ks < 4; ks++) {
            wmma::fragment<wmma::matrix_a, 16, 16, 8, wmma::precision::tf32, wmma::row_major> af[2];
            wmma::fragment<wmma::matrix_b, 16, 16, 8, wmma::precision::tf32, wmma::col_major> bf[4];
#pragma unroll
            for (int mt = 0; mt < 2; mt++) {
                wmma::load_matrix_sync(af[mt], As + (wm * 32 + mt * 16) * SM_STRIDE + ks * 8, SM_STRIDE);
#pragma unroll
                for (int e = 0; e < af[mt].num_elements; e++)
                    af[mt].x[e] = wmma::__float_to_tf32(af[mt].x[e]);
            }
#pragma unroll
            for (int nt = 0; nt < 4; nt++) {
                wmma::load_matrix_sync(bf[nt], Bs + (wn * 64 + nt * 16) * SM_STRIDE + ks * 8, SM_STRIDE);
#pragma unroll
                for (int e = 0; e < bf[nt].num_elements; e++)
                    bf[nt].x[e] = wmma::__float_to_tf32(bf[nt].x[e]);
            }
#pragma unroll
            for (int mt = 0; mt < 2; mt++)
#pragma unroll
                for (int nt = 0; nt < 4; nt++)
                    wmma::mma_sync(acc[mt][nt], af[mt], bf[nt], acc[mt][nt]);
        }
        __syncthreads();
    }

    const int colbase = blockIdx.y * 128 + wn * 64;
#pragma unroll
    for (int mt = 0; mt < 2; mt++) {
        const size_t row = rowbase + wm * 32 + mt * 16;
#pragma unroll
        for (int nt = 0; nt < 4; nt++)
            wmma::store_matrix_sync(g_proj + row * 256 + colbase + nt * 16,
                                    acc[mt][nt], 256, wmma::mem_row_major);
    }
}

// ---------------- mean-aggregate (gather) + bias + lin_r + ReLU ----------------
__global__ void gather_kernel(const float* __restrict__ bias, int osel) {
    int gw   = (blockIdx.x * blockDim.x + threadIdx.x) >> 5;
    int lane = threadIdx.x & 31;
    if (gw >= NA) return;

    int deg = g_cnt[gw];
    int dcl = min(deg, MAXDEG);
    int src_l = (lane < dcl) ? g_inc[(size_t)gw * MAXDEG + lane] : 0;

    float4 acc = make_float4(0.f, 0.f, 0.f, 0.f);
    for (int p = 0; p < dcl; p++) {
        int src = (p < 32) ? __shfl_sync(0xffffffffu, src_l, p)
                           : g_inc[(size_t)gw * MAXDEG + p];
        float4 h = *(const float4*)(g_proj + (size_t)src * 256 + lane * 4);
        acc.x += h.x; acc.y += h.y; acc.z += h.z; acc.w += h.w;
    }
    float inv = 1.f / (float)max(deg, 1);
    float4 pr = *(const float4*)(g_proj + (size_t)gw * 256 + 128 + lane * 4);
    float4 bb = *(const float4*)(bias + lane * 4);
    float4 o;
    o.x = fmaxf(fmaf(acc.x, inv, bb.x + pr.x), 0.f);
    o.y = fmaxf(fmaf(acc.y, inv, bb.y + pr.y), 0.f);
    o.z = fmaxf(fmaf(acc.z, inv, bb.z + pr.z), 0.f);
    o.w = fmaxf(fmaf(acc.w, inv, bb.w + pr.w), 0.f);
    float* out = osel ? g_ao : g_bo;
    *(float4*)(out + (size_t)gw * HID + lane * 4) = o;
}

// ---------------- crystal mean-pool + linear head ----------------
__global__ void pool_kernel(const int* __restrict__ crys,
                            const float* __restrict__ Wfc, const float* __restrict__ bfc,
                            float* __restrict__ out) {
    int b = blockIdx.x;
    int f = threadIdx.x;
    int start = crys[b * 2], end = crys[b * 2 + 1];
    const float* src = (f < 128) ? g_bo : g_ao;
    int fo = (f < 128) ? f : (f - 128);
    float s = 0.f;
    for (int a = start; a < end; a++) s += src[(size_t)a * HID + fo];
    __shared__ float pooled[256];
    pooled[f] = s / (float)(end - start);
    __syncthreads();
    int wid = f >> 5, lane = f & 31;
    if (wid < 2) {
        float d = 0.f;
        for (int i = lane; i < 256; i += 32) d += pooled[i] * Wfc[wid * 256 + i];
#pragma unroll
        for (int off = 16; off; off >>= 1) d += __shfl_down_sync(0xffffffffu, d, off);
        if (lane == 0) out[b * 2 + wid] = d + bfc[wid];
    }
}

// ---------------- host launcher ----------------
extern "C" void kernel_launch(void* const* d_in, const int* in_sizes, int n_in,
                              void* d_out, int out_size) {
    if (n_in < 19) return;

    int I_bond, I_angle, I_W1b, I_b1b, I_W1br, I_W1a, I_b1a, I_W1ar,
        I_W2b, I_b2b, I_W2br, I_W2a, I_b2a, I_W2ar, I_Wfc, I_bfc, I_nbr, I_crys;

    if (in_sizes[0] == 600000 && in_sizes[2] == 50000) {
        I_bond = 0; I_angle = 1; I_nbr = 3; I_crys = 4;
        I_W1b = 5;  I_b1b = 6;  I_W1br = 7;  I_W1a = 8;  I_b1a = 9;  I_W1ar = 10;
        I_W2b = 11; I_b2b = 12; I_W2br = 13; I_W2a = 14; I_b2a = 15; I_W2ar = 16;
        I_Wfc = 17; I_bfc = 18;
    } else if (in_sizes[0] == 600000) {
        I_bond = 0; I_angle = 1; I_W1b = 2; I_b1b = 3; I_W1br = 4;
        I_W1a = 5;  I_b1a = 6;  I_W1ar = 7; I_W2b = 8; I_b2b = 9; I_W2br = 10;
        I_W2a = 11; I_b2a = 12; I_W2ar = 13; I_Wfc = 14; I_bfc = 15;
        I_nbr = 17; I_crys = 18;
    } else {
        I_W1a = 0; I_W1ar = 1; I_W1b = 2; I_W1br = 3;
        I_W2a = 4; I_W2ar = 5; I_W2b = 6; I_W2br = 7; I_Wfc = 8;
        I_angle = 9; I_b1a = 10; I_b1b = 11; I_b2a = 12; I_b2b = 13; I_bfc = 14;
        I_bond = 15; I_crys = 16; I_nbr = 17;
    }

    const float* bond  = (const float*)d_in[I_bond];
    const float* angle = (const float*)d_in[I_angle];
    const int*   nbr   = (const int*)  d_in[I_nbr];
    const int*   crys  = (const int*)  d_in[I_crys];
    const float* W1b   = (const float*)d_in[I_W1b];
    const float* b1b   = (const float*)d_in[I_b1b];
    const float* W1br  = (const float*)d_in[I_W1br];
    const float* W1a   = (const float*)d_in[I_W1a];
    const float* b1a   = (const float*)d_in[I_b1a];
    const float* W1ar  = (const float*)d_in[I_W1ar];
    const float* W2b   = (const float*)d_in[I_W2b];
    const float* b2b   = (const float*)d_in[I_b2b];
    const float* W2br  = (const float*)d_in[I_W2br];
    const float* W2a   = (const float*)d_in[I_W2a];
    const float* b2a   = (const float*)d_in[I_b2a];
    const float* W2ar  = (const float*)d_in[I_W2ar];
    const float* Wfc   = (const float*)d_in[I_Wfc];
    const float* bfc   = (const float*)d_in[I_bfc];
    float* out = (float*)d_out;

    cudaFuncSetAttribute(wmma_gemm_kernel, cudaFuncAttributeMaxDynamicSharedMemorySize, SM_TOTAL);

    const int gatherBlocks = (NA * 32 + 255) / 256;
    const dim3 ggemm(MPAD / 128, 2);

    zero_cnt_kernel<<<(NA + 255) / 256, 256>>>();
    count_kernel<<<(NEDGE + 255) / 256, 256>>>(nbr);

    // ---- layer 1, bond path: K=480 (steps=40, nper=12) ----
    {
        long total = (long)MPAD * 480;
        expand_kernel<40, 12><<<(unsigned)((total + 255) / 256), 256>>>(
            bond, 0.f, 8.f / 39.f, 25.f, total);
    }
    wmma_gemm_kernel<<<ggemm, 256, SM_TOTAL>>>(0, W1b, W1br, 480);
    gather_kernel<<<gatherBlocks, 256>>>(b1b, 0);

    // ---- layer 1, angle path: K=1440 (steps=10, nper=144) ----
    {
        long total = (long)MPAD * 1440;
        expand_kernel<10, 144><<<(unsigned)((total + 255) / 256), 256>>>(
            angle, -1.f, 2.f / 9.f, 25.f, total);
    }
    wmma_gemm_kernel<<<ggemm, 256, SM_TOTAL>>>(0, W1a, W1ar, 1440);
    gather_kernel<<<gatherBlocks, 256>>>(b1a, 1);

    // ---- layer 2, bond path: K=128 ----
    wmma_gemm_kernel<<<ggemm, 256, SM_TOTAL>>>(1, W2b, W2br, 128);
    gather_kernel<<<gatherBlocks, 256>>>(b2b, 0);

    // ---- layer 2, angle path: K=128 ----
    wmma_gemm_kernel<<<ggemm, 256, SM_TOTAL>>>(2, W2a, W2ar, 128);
    gather_kernel<<<gatherBlocks, 256>>>(b2a, 1);

    // ---- pool + head ----
    pool_kernel<<<500, 256>>>(crys, Wfc, bfc, out);
}

// round 7
// speedup vs baseline: 2.3579x; 1.5929x over previous
#include <cuda_runtime.h>
#include <cuda_fp16.h>
#include <cstdint>
#include <mma.h>

using namespace nvcuda;

// ---------------- problem constants ----------------
#define NA     50000
#define MPAD   50048            // 391 * 128
#define NEIGH  12
#define NEDGE  (NA * NEIGH)
#define MAXDEG 64
#define HID    128

// ---------------- scratch (static device globals; no allocation) ----------------
__device__ float g_exp [(size_t)MPAD * 1440];   // expanded features (bond reuses prefix)
__device__ float g_proj[(size_t)MPAD * 256];    // [proj_l | proj_r]
__device__ float g_bo  [(size_t)MPAD * HID];
__device__ float g_ao  [(size_t)MPAD * HID];
__device__ int   g_cnt [NA];
__device__ int   g_inc [(size_t)NA * MAXDEG];   // ELL incoming-edge source lists

// ---------------- graph inversion ----------------
__global__ void zero_cnt_kernel() {
    int i = blockIdx.x * blockDim.x + threadIdx.x;
    if (i < NA) g_cnt[i] = 0;
}
__global__ void count_kernel(const int* __restrict__ nbr) {
    int e = blockIdx.x * blockDim.x + threadIdx.x;
    if (e >= NEDGE) return;
    int d = nbr[e];
    int p = atomicAdd(&g_cnt[d], 1);
    if (p < MAXDEG) g_inc[(size_t)d * MAXDEG + p] = e / NEIGH;
}

// ---------------- full-range exp on FMA/ALU pipes (for x <= 0) ----------------
__device__ __forceinline__ float fast_exp(float x) {
    float t = x * 1.4426950408889634f;                 // x * log2(e)
    int   n = __float2int_rn(t);
    float r = (t - (float)n) * 0.6931471805599453f;    // r in [-0.347, 0.347]
    float p = fmaf(r, 1.f/720.f, 1.f/120.f);           // degree-6 Taylor of e^r
    p = fmaf(p, r, 1.f/24.f);
    p = fmaf(p, r, 1.f/6.f);
    p = fmaf(p, r, 0.5f);
    p = fmaf(p, r, 1.f);
    p = fmaf(p, r, 1.f);
    int e = n + 127;
    float s = __int_as_float(max(e, 0) << 23);         // 2^n, flush to 0 below 2^-127
    return p * s;
}

// ---------------- Gaussian basis expansion ----------------
template<int STEPS, int NPER>
__global__ void expand_kernel(const float* __restrict__ fea,
                              float mu0, float dmu, float inv_g2, long total) {
    long idx = (long)blockIdx.x * blockDim.x + threadIdx.x;
    if (idx >= total) return;
    int  s  = (int)(idx % STEPS);
    long np = idx / STEPS;
    long n  = np / NPER;
    float v = 0.f;
    if (n < NA) {
        float a = fea[np];
        float d = a - fmaf((float)s, dmu, mu0);
        v = fast_exp(-d * d * inv_g2);
    }
    g_exp[idx] = v;
}

// ---------------- cp.async helpers ----------------
__device__ __forceinline__ uint32_t smem_u32(const void* p) {
    uint32_t a;
    asm("{ .reg .u64 t; cvta.to.shared.u64 t, %1; cvt.u32.u64 %0, t; }" : "=r"(a) : "l"(p));
    return a;
}
#define CP_ASYNC16(dst, src) \
    asm volatile("cp.async.cg.shared.global [%0], [%1], 16;" :: "r"(dst), "l"(src))
#define CP_COMMIT()  asm volatile("cp.async.commit_group;" ::: "memory")
#define CP_WAIT(n)   asm volatile("cp.async.wait_group %0;" :: "n"(n) : "memory")

// ---------------- fp16 wmma GEMM: g_proj[M, y*128..] = A[M,K] @ W^T ----------------
// cp.async fp32 double-buffer -> in-smem RN convert to fp16 tiles -> m16n16k16 HMMA.
// fp16 mantissa (10 bits) == tf32 mantissa; fp32 accumulate => same numerics as tf32.
#define SMF_STRIDE 36                       // fp32 staging stride (floats)
#define SMF_TILE   (128 * SMF_STRIDE)       // floats per staging tile
#define SMH_STRIDE 40                       // fp16 tile stride (halves); 80B rows, LDSM-friendly
#define SMH_TILE   (128 * SMH_STRIDE)       // halves per fp16 tile
#define SM_TOTAL   (4 * SMF_TILE * 4 + 2 * SMH_TILE * 2)   // 73728 + 20480 = 94208 bytes

__global__ void __launch_bounds__(256, 2)
hgemm_kernel(int asel, const float* __restrict__ Wl, const float* __restrict__ Wr, int K)
{
    extern __shared__ float sm[];
    float* const FA[2] = { sm,                sm + SMF_TILE };
    float* const FB[2] = { sm + 2 * SMF_TILE, sm + 3 * SMF_TILE };
    __half* const HA = (__half*)(sm + 4 * SMF_TILE);
    __half* const HB = HA + SMH_TILE;

    const float* __restrict__ A = (asel == 0) ? g_exp : (asel == 1 ? g_bo : g_ao);
    const float* __restrict__ W = blockIdx.y ? Wr : Wl;

    const int tid  = threadIdx.x;
    const int row8 = tid >> 3;          // 0..31 loader row base
    const int c4   = (tid & 7) << 2;    // 0,4,...,28

    const size_t rowbase = (size_t)blockIdx.x * 128;
    const int T = K >> 5;

    const float* aSrc = A + (rowbase + row8) * (size_t)K + c4;
    const float* bSrc = W + (size_t)row8 * K + c4;
    const uint32_t aDst0 = smem_u32(FA[0]) + (row8 * SMF_STRIDE + c4) * 4;
    const uint32_t bDst0 = smem_u32(FB[0]) + (row8 * SMF_STRIDE + c4) * 4;
    const uint32_t bufStep  = SMF_TILE * 4;
    const size_t   rowStepA = 32 * (size_t)K;
    const uint32_t rowStepS = 32 * SMF_STRIDE * 4;

    // prefetch chunk 0
#pragma unroll
    for (int i = 0; i < 4; i++) {
        CP_ASYNC16(aDst0 + i * rowStepS, aSrc + i * rowStepA);
        CP_ASYNC16(bDst0 + i * rowStepS, bSrc + i * rowStepA);
    }
    CP_COMMIT();

    const int warp = tid >> 5;
    const int wm = warp >> 1;           // 0..3 : 32-row slice
    const int wn = warp & 1;            // 0..1 : 64-col slice

    // convert-pass addressing: 2 threads per row, 16 floats each
    const int cr  = tid >> 1;           // 0..127
    const int ck  = (tid & 1) << 4;     // 0 or 16

    wmma::fragment<wmma::accumulator, 16, 16, 16, float> acc[2][4];
#pragma unroll
    for (int i = 0; i < 2; i++)
#pragma unroll
        for (int j = 0; j < 4; j++) wmma::fill_fragment(acc[i][j], 0.f);

    for (int t = 0; t < T; t++) {
        const int b = t & 1;
        if (t + 1 < T) {
            const int nb = (t + 1) & 1;
            const int k0 = (t + 1) << 5;
#pragma unroll
            for (int i = 0; i < 4; i++) {
                CP_ASYNC16(aDst0 + nb * bufStep + i * rowStepS, aSrc + k0 + i * rowStepA);
                CP_ASYNC16(bDst0 + nb * bufStep + i * rowStepS, bSrc + k0 + i * rowStepA);
            }
            CP_COMMIT();
            CP_WAIT(1);
        } else {
            CP_WAIT(0);
        }
        __syncthreads();   // staging chunk t visible; all warps done with H from t-1

        // convert fp32 staging -> fp16 tiles (RN), each element exactly once
        {
            const float* fa = FA[b] + cr * SMF_STRIDE + ck;
            const float* fb = FB[b] + cr * SMF_STRIDE + ck;
            __half2 ha[8], hb[8];
#pragma unroll
            for (int i = 0; i < 4; i++) {
                float4 va = *(const float4*)(fa + i * 4);
                float4 vb = *(const float4*)(fb + i * 4);
                ha[i * 2 + 0] = __floats2half2_rn(va.x, va.y);
                ha[i * 2 + 1] = __floats2half2_rn(va.z, va.w);
                hb[i * 2 + 0] = __floats2half2_rn(vb.x, vb.y);
                hb[i * 2 + 1] = __floats2half2_rn(vb.z, vb.w);
            }
            __half* pa = HA + cr * SMH_STRIDE + ck;
            __half* pb = HB + cr * SMH_STRIDE + ck;
            *(uint4*)(pa)     = *(uint4*)&ha[0];
            *(uint4*)(pa + 8) = *(uint4*)&ha[4];
            *(uint4*)(pb)     = *(uint4*)&hb[0];
            *(uint4*)(pb + 8) = *(uint4*)&hb[4];
        }
        __syncthreads();   // fp16 tiles ready

#pragma unroll
        for (int ks = 0; ks < 2; ks++) {
            wmma::fragment<wmma::matrix_a, 16, 16, 16, __half, wmma::row_major> af[2];
            wmma::fragment<wmma::matrix_b, 16, 16, 16, __half, wmma::col_major> bf[4];
#pragma unroll
            for (int mt = 0; mt < 2; mt++)
                wmma::load_matrix_sync(af[mt], HA + (wm * 32 + mt * 16) * SMH_STRIDE + ks * 16, SMH_STRIDE);
#pragma unroll
            for (int nt = 0; nt < 4; nt++)
                wmma::load_matrix_sync(bf[nt], HB + (wn * 64 + nt * 16) * SMH_STRIDE + ks * 16, SMH_STRIDE);
#pragma unroll
            for (int mt = 0; mt < 2; mt++)
#pragma unroll
                for (int nt = 0; nt < 4; nt++)
                    wmma::mma_sync(acc[mt][nt], af[mt], bf[nt], acc[mt][nt]);
        }
    }

    const int colbase = blockIdx.y * 128 + wn * 64;
#pragma unroll
    for (int mt = 0; mt < 2; mt++) {
        const size_t row = rowbase + wm * 32 + mt * 16;
#pragma unroll
        for (int nt = 0; nt < 4; nt++)
            wmma::store_matrix_sync(g_proj + row * 256 + colbase + nt * 16,
                                    acc[mt][nt], 256, wmma::mem_row_major);
    }
}

// ---------------- mean-aggregate (gather) + bias + lin_r + ReLU ----------------
__global__ void gather_kernel(const float* __restrict__ bias, int osel) {
    int gw   = (blockIdx.x * blockDim.x + threadIdx.x) >> 5;
    int lane = threadIdx.x & 31;
    if (gw >= NA) return;

    int deg = g_cnt[gw];
    int dcl = min(deg, MAXDEG);
    int src_l = (lane < dcl) ? g_inc[(size_t)gw * MAXDEG + lane] : 0;

    float4 acc = make_float4(0.f, 0.f, 0.f, 0.f);
    for (int p = 0; p < dcl; p++) {
        int src = (p < 32) ? __shfl_sync(0xffffffffu, src_l, p)
                           : g_inc[(size_t)gw * MAXDEG + p];
        float4 h = *(const float4*)(g_proj + (size_t)src * 256 + lane * 4);
        acc.x += h.x; acc.y += h.y; acc.z += h.z; acc.w += h.w;
    }
    float inv = 1.f / (float)max(deg, 1);
    float4 pr = *(const float4*)(g_proj + (size_t)gw * 256 + 128 + lane * 4);
    float4 bb = *(const float4*)(bias + lane * 4);
    float4 o;
    o.x = fmaxf(fmaf(acc.x, inv, bb.x + pr.x), 0.f);
    o.y = fmaxf(fmaf(acc.y, inv, bb.y + pr.y), 0.f);
    o.z = fmaxf(fmaf(acc.z, inv, bb.z + pr.z), 0.f);
    o.w = fmaxf(fmaf(acc.w, inv, bb.w + pr.w), 0.f);
    float* out = osel ? g_ao : g_bo;
    *(float4*)(out + (size_t)gw * HID + lane * 4) = o;
}

// ---------------- crystal mean-pool + linear head ----------------
__global__ void pool_kernel(const int* __restrict__ crys,
                            const float* __restrict__ Wfc, const float* __restrict__ bfc,
                            float* __restrict__ out) {
    int b = blockIdx.x;
    int f = threadIdx.x;
    int start = crys[b * 2], end = crys[b * 2 + 1];
    const float* src = (f < 128) ? g_bo : g_ao;
    int fo = (f < 128) ? f : (f - 128);
    float s = 0.f;
    for (int a = start; a < end; a++) s += src[(size_t)a * HID + fo];
    __shared__ float pooled[256];
    pooled[f] = s / (float)(end - start);
    __syncthreads();
    int wid = f >> 5, lane = f & 31;
    if (wid < 2) {
        float d = 0.f;
        for (int i = lane; i < 256; i += 32) d += pooled[i] * Wfc[wid * 256 + i];
#pragma unroll
        for (int off = 16; off; off >>= 1) d += __shfl_down_sync(0xffffffffu, d, off);
        if (lane == 0) out[b * 2 + wid] = d + bfc[wid];
    }
}

// ---------------- host launcher ----------------
extern "C" void kernel_launch(void* const* d_in, const int* in_sizes, int n_in,
                              void* d_out, int out_size) {
    if (n_in < 19) return;

    int I_bond, I_angle, I_W1b, I_b1b, I_W1br, I_W1a, I_b1a, I_W1ar,
        I_W2b, I_b2b, I_W2br, I_W2a, I_b2a, I_W2ar, I_Wfc, I_bfc, I_nbr, I_crys;

    if (in_sizes[0] == 600000 && in_sizes[2] == 50000) {
        I_bond = 0; I_angle = 1; I_nbr = 3; I_crys = 4;
        I_W1b = 5;  I_b1b = 6;  I_W1br = 7;  I_W1a = 8;  I_b1a = 9;  I_W1ar = 10;
        I_W2b = 11; I_b2b = 12; I_W2br = 13; I_W2a = 14; I_b2a = 15; I_W2ar = 16;
        I_Wfc = 17; I_bfc = 18;
    } else if (in_sizes[0] == 600000) {
        I_bond = 0; I_angle = 1; I_W1b = 2; I_b1b = 3; I_W1br = 4;
        I_W1a = 5;  I_b1a = 6;  I_W1ar = 7; I_W2b = 8; I_b2b = 9; I_W2br = 10;
        I_W2a = 11; I_b2a = 12; I_W2ar = 13; I_Wfc = 14; I_bfc = 15;
        I_nbr = 17; I_crys = 18;
    } else {
        I_W1a = 0; I_W1ar = 1; I_W1b = 2; I_W1br = 3;
        I_W2a = 4; I_W2ar = 5; I_W2b = 6; I_W2br = 7; I_Wfc = 8;
        I_angle = 9; I_b1a = 10; I_b1b = 11; I_b2a = 12; I_b2b = 13; I_bfc = 14;
        I_bond = 15; I_crys = 16; I_nbr = 17;
    }

    const float* bond  = (const float*)d_in[I_bond];
    const float* angle = (const float*)d_in[I_angle];
    const int*   nbr   = (const int*)  d_in[I_nbr];
    const int*   crys  = (const int*)  d_in[I_crys];
    const float* W1b   = (const float*)d_in[I_W1b];
    const float* b1b   = (const float*)d_in[I_b1b];
    const float* W1br  = (const float*)d_in[I_W1br];
    const float* W1a   = (const float*)d_in[I_W1a];
    const float* b1a   = (const float*)d_in[I_b1a];
    const float* W1ar  = (const float*)d_in[I_W1ar];
    const float* W2b   = (const float*)d_in[I_W2b];
    const float* b2b   = (const float*)d_in[I_b2b];
    const float* W2br  = (const float*)d_in[I_W2br];
    const float* W2a   = (const float*)d_in[I_W2a];
    const float* b2a   = (const float*)d_in[I_b2a];
    const float* W2ar  = (const float*)d_in[I_W2ar];
    const float* Wfc   = (const float*)d_in[I_Wfc];
    const float* bfc   = (const float*)d_in[I_bfc];
    float* out = (float*)d_out;

    cudaFuncSetAttribute(hgemm_kernel, cudaFuncAttributeMaxDynamicSharedMemorySize, SM_TOTAL);

    const int gatherBlocks = (NA * 32 + 255) / 256;
    const dim3 ggemm(MPAD / 128, 2);

    zero_cnt_kernel<<<(NA + 255) / 256, 256>>>();
    count_kernel<<<(NEDGE + 255) / 256, 256>>>(nbr);

    // ---- layer 1, bond path: K=480 (steps=40, nper=12) ----
    {
        long total = (long)MPAD * 480;
        expand_kernel<40, 12><<<(unsigned)((total + 255) / 256), 256>>>(
            bond, 0.f, 8.f / 39.f, 25.f, total);
    }
    hgemm_kernel<<<ggemm, 256, SM_TOTAL>>>(0, W1b, W1br, 480);
    gather_kernel<<<gatherBlocks, 256>>>(b1b, 0);

    // ---- layer 1, angle path: K=1440 (steps=10, nper=144) ----
    {
        long total = (long)MPAD * 1440;
        expand_kernel<10, 144><<<(unsigned)((total + 255) / 256), 256>>>(
            angle, -1.f, 2.f / 9.f, 25.f, total);
    }
    hgemm_kernel<<<ggemm, 256, SM_TOTAL>>>(0, W1a, W1ar, 1440);
    gather_kernel<<<gatherBlocks, 256>>>(b1a, 1);

    // ---- layer 2, bond path: K=128 ----
    hgemm_kernel<<<ggemm, 256, SM_TOTAL>>>(1, W2b, W2br, 128);
    gather_kernel<<<gatherBlocks, 256>>>(b2b, 0);

    // ---- layer 2, angle path: K=128 ----
    hgemm_kernel<<<ggemm, 256, SM_TOTAL>>>(2, W2a, W2ar, 128);
    gather_kernel<<<gatherBlocks, 256>>>(b2a, 1);

    // ---- pool + head ----
    pool_kernel<<<500, 256>>>(crys, Wfc, bfc, out);
}

// round 8
// speedup vs baseline: 2.7410x; 1.1625x over previous
#include <cuda_runtime.h>
#include <cuda_fp16.h>
#include <cstdint>
#include <mma.h>

using namespace nvcuda;

// ---------------- problem constants ----------------
#define NA     50000
#define MPAD   50048            // 391 * 128
#define NEIGH  12
#define NEDGE  (NA * NEIGH)
#define MAXDEG 64
#define HID    128

// ---------------- scratch (static device globals; no allocation) ----------------
__device__ float g_proj[(size_t)MPAD * 256];    // [proj_l | proj_r]
__device__ float g_bo  [(size_t)MPAD * HID];
__device__ float g_ao  [(size_t)MPAD * HID];
__device__ int   g_cnt [NA];
__device__ int   g_inc [(size_t)NA * MAXDEG];   // ELL incoming-edge source lists

// ---------------- graph inversion ----------------
__global__ void zero_cnt_kernel() {
    int i = blockIdx.x * blockDim.x + threadIdx.x;
    if (i < NA) g_cnt[i] = 0;
}
__global__ void count_kernel(const int* __restrict__ nbr) {
    int e = blockIdx.x * blockDim.x + threadIdx.x;
    if (e >= NEDGE) return;
    int d = nbr[e];
    int p = atomicAdd(&g_cnt[d], 1);
    if (p < MAXDEG) g_inc[(size_t)d * MAXDEG + p] = e / NEIGH;
}

// ---------------- full-range exp on FMA/ALU pipes (for x <= 0) ----------------
__device__ __forceinline__ float fast_exp(float x) {
    float t = x * 1.4426950408889634f;                 // x * log2(e)
    int   n = __float2int_rn(t);
    float r = (t - (float)n) * 0.6931471805599453f;    // r in [-0.347, 0.347]
    float p = fmaf(r, 1.f/720.f, 1.f/120.f);           // degree-6 Taylor of e^r
    p = fmaf(p, r, 1.f/24.f);
    p = fmaf(p, r, 1.f/6.f);
    p = fmaf(p, r, 0.5f);
    p = fmaf(p, r, 1.f);
    p = fmaf(p, r, 1.f);
    int e = n + 127;
    float s = __int_as_float(max(e, 0) << 23);         // 2^n, flush to 0 below 2^-127
    return p * s;
}

// ---------------- cp.async helpers ----------------
__device__ __forceinline__ uint32_t smem_u32(const void* p) {
    uint32_t a;
    asm("{ .reg .u64 t; cvta.to.shared.u64 t, %1; cvt.u32.u64 %0, t; }" : "=r"(a) : "l"(p));
    return a;
}
#define CP_ASYNC16(dst, src) \
    asm volatile("cp.async.cg.shared.global [%0], [%1], 16;" :: "r"(dst), "l"(src))
#define CP_COMMIT()  asm volatile("cp.async.commit_group;" ::: "memory")
#define CP_WAIT(n)   asm volatile("cp.async.wait_group %0;" :: "n"(n) : "memory")

// ---------------- fused fp16 wmma GEMM: g_proj[M, y*128..] = A[M,K] @ W^T ----------------
// MODE 0: A generated in-smem from raw features (Gaussian basis, fast_exp) -> no A traffic.
// MODE 1/2: A loaded from g_bo/g_ao via cp.async fp32 staging + fp16 convert.
// B always cp.async fp32 staging + fp16 convert. m16n16k16 HMMA, fp32 accumulate.
#define SMF_STRIDE 36                       // fp32 staging stride (floats)
#define SMF_TILE   (128 * SMF_STRIDE)       // floats per staging tile
#define SMH_STRIDE 40                       // fp16 tile stride (halves)
#define SMH_TILE   (128 * SMH_STRIDE)       // halves per fp16 tile
#define SM_TOTAL   (4 * SMF_TILE * 4 + 2 * SMH_TILE * 2)   // 94208 bytes

template<int MODE, int STEPS, int NPER>
__global__ void __launch_bounds__(256, 2)
hgemm_kernel(const float* __restrict__ Wl, const float* __restrict__ Wr,
             const float* __restrict__ fea, int K,
             float mu0, float dmu, float ig2)
{
    extern __shared__ float sm[];
    float* const FA[2] = { sm,                sm + SMF_TILE };
    float* const FB[2] = { sm + 2 * SMF_TILE, sm + 3 * SMF_TILE };
    __half* const HA = (__half*)(sm + 4 * SMF_TILE);
    __half* const HB = HA + SMH_TILE;

    const float* __restrict__ A = (MODE == 1) ? g_bo : g_ao;   // load modes only
    const float* __restrict__ W = blockIdx.y ? Wr : Wl;

    const int tid  = threadIdx.x;
    const int row8 = tid >> 3;          // 0..31 loader row base
    const int c4   = (tid & 7) << 2;    // 0,4,...,28

    const size_t rowbase = (size_t)blockIdx.x * 128;
    const int T = K >> 5;

    const float* aSrc = A + (rowbase + row8) * (size_t)K + c4;
    const float* bSrc = W + (size_t)row8 * K + c4;
    const uint32_t aDst0 = smem_u32(FA[0]) + (row8 * SMF_STRIDE + c4) * 4;
    const uint32_t bDst0 = smem_u32(FB[0]) + (row8 * SMF_STRIDE + c4) * 4;
    const uint32_t bufStep  = SMF_TILE * 4;
    const size_t   rowStepA = 32 * (size_t)K;
    const uint32_t rowStepS = 32 * SMF_STRIDE * 4;

    // prefetch chunk 0
#pragma unroll
    for (int i = 0; i < 4; i++) {
        if (MODE != 0) CP_ASYNC16(aDst0 + i * rowStepS, aSrc + i * rowStepA);
        CP_ASYNC16(bDst0 + i * rowStepS, bSrc + i * rowStepA);
    }
    CP_COMMIT();

    const int warp = tid >> 5;
    const int wm = warp >> 1;           // 0..3 : 32-row slice
    const int wn = warp & 1;            // 0..1 : 64-col slice

    // convert/generate addressing: 2 threads per row, 16 values each
    const int cr  = tid >> 1;           // 0..127
    const int ck  = (tid & 1) << 4;     // 0 or 16
    const long grow = (long)rowbase + cr;
    const bool valid = grow < NA;
    const float* feaRow = (MODE == 0)
        ? fea + (size_t)(valid ? grow : 0) * NPER : (const float*)0;

    wmma::fragment<wmma::accumulator, 16, 16, 16, float> acc[2][4];
#pragma unroll
    for (int i = 0; i < 2; i++)
#pragma unroll
        for (int j = 0; j < 4; j++) wmma::fill_fragment(acc[i][j], 0.f);

    for (int t = 0; t < T; t++) {
        const int b = t & 1;
        if (t + 1 < T) {
            const int nb = (t + 1) & 1;
            const int k0 = (t + 1) << 5;
#pragma unroll
            for (int i = 0; i < 4; i++) {
                if (MODE != 0) CP_ASYNC16(aDst0 + nb * bufStep + i * rowStepS, aSrc + k0 + i * rowStepA);
                CP_ASYNC16(bDst0 + nb * bufStep + i * rowStepS, bSrc + k0 + i * rowStepA);
            }
            CP_COMMIT();
            CP_WAIT(1);
        } else {
            CP_WAIT(0);
        }
        __syncthreads();   // staging visible; all warps done reading HA/HB of t-1

        if (MODE == 0) {
            // generate A tile: Gaussian basis expansion, identical math to expand+round
            const int kb = (t << 5) + ck;
            __half2 hh[8];
#pragma unroll
            for (int j = 0; j < 16; j += 2) {
                int k0j = kb + j, k1j = kb + j + 1;
                int p0 = k0j / STEPS, s0 = k0j - p0 * STEPS;
                int p1 = k1j / STEPS, s1 = k1j - p1 * STEPS;
                float a0 = feaRow[p0], a1 = feaRow[p1];
                float d0 = a0 - fmaf((float)s0, dmu, mu0);
                float d1 = a1 - fmaf((float)s1, dmu, mu0);
                float v0 = fast_exp(-d0 * d0 * ig2);
                float v1 = fast_exp(-d1 * d1 * ig2);
                if (!valid) { v0 = 0.f; v1 = 0.f; }
                hh[j >> 1] = __floats2half2_rn(v0, v1);
            }
            __half* pa = HA + cr * SMH_STRIDE + ck;
            *(uint4*)(pa)     = *(uint4*)&hh[0];
            *(uint4*)(pa + 8) = *(uint4*)&hh[4];
        } else {
            const float* fa = FA[b] + cr * SMF_STRIDE + ck;
            __half2 ha[8];
#pragma unroll
            for (int i = 0; i < 4; i++) {
                float4 va = *(const float4*)(fa + i * 4);
                ha[i * 2 + 0] = __floats2half2_rn(va.x, va.y);
                ha[i * 2 + 1] = __floats2half2_rn(va.z, va.w);
            }
            __half* pa = HA + cr * SMH_STRIDE + ck;
            *(uint4*)(pa)     = *(uint4*)&ha[0];
            *(uint4*)(pa + 8) = *(uint4*)&ha[4];
        }
        {
            const float* fb = FB[b] + cr * SMF_STRIDE + ck;
            __half2 hb[8];
#pragma unroll
            for (int i = 0; i < 4; i++) {
                float4 vb = *(const float4*)(fb + i * 4);
                hb[i * 2 + 0] = __floats2half2_rn(vb.x, vb.y);
                hb[i * 2 + 1] = __floats2half2_rn(vb.z, vb.w);
            }
            __half* pb = HB + cr * SMH_STRIDE + ck;
            *(uint4*)(pb)     = *(uint4*)&hb[0];
            *(uint4*)(pb + 8) = *(uint4*)&hb[4];
        }
        __syncthreads();   // fp16 tiles ready

#pragma unroll
        for (int ks = 0; ks < 2; ks++) {
            wmma::fragment<wmma::matrix_a, 16, 16, 16, __half, wmma::row_major> af[2];
            wmma::fragment<wmma::matrix_b, 16, 16, 16, __half, wmma::col_major> bf[4];
#pragma unroll
            for (int mt = 0; mt < 2; mt++)
                wmma::load_matrix_sync(af[mt], HA + (wm * 32 + mt * 16) * SMH_STRIDE + ks * 16, SMH_STRIDE);
#pragma unroll
            for (int nt = 0; nt < 4; nt++)
                wmma::load_matrix_sync(bf[nt], HB + (wn * 64 + nt * 16) * SMH_STRIDE + ks * 16, SMH_STRIDE);
#pragma unroll
            for (int mt = 0; mt < 2; mt++)
#pragma unroll
                for (int nt = 0; nt < 4; nt++)
                    wmma::mma_sync(acc[mt][nt], af[mt], bf[nt], acc[mt][nt]);
        }
    }

    const int colbase = blockIdx.y * 128 + wn * 64;
#pragma unroll
    for (int mt = 0; mt < 2; mt++) {
        const size_t row = rowbase + wm * 32 + mt * 16;
#pragma unroll
        for (int nt = 0; nt < 4; nt++)
            wmma::store_matrix_sync(g_proj + row * 256 + colbase + nt * 16,
                                    acc[mt][nt], 256, wmma::mem_row_major);
    }
}

// ---------------- mean-aggregate (gather) + bias + lin_r + ReLU ----------------
__global__ void gather_kernel(const float* __restrict__ bias, int osel) {
    int gw   = (blockIdx.x * blockDim.x + threadIdx.x) >> 5;
    int lane = threadIdx.x & 31;
    if (gw >= NA) return;

    int deg = g_cnt[gw];
    int dcl = min(deg, MAXDEG);
    int src_l = (lane < dcl) ? g_inc[(size_t)gw * MAXDEG + lane] : 0;

    float4 acc = make_float4(0.f, 0.f, 0.f, 0.f);
    for (int p = 0; p < dcl; p++) {
        int src = (p < 32) ? __shfl_sync(0xffffffffu, src_l, p)
                           : g_inc[(size_t)gw * MAXDEG + p];
        float4 h = *(const float4*)(g_proj + (size_t)src * 256 + lane * 4);
        acc.x += h.x; acc.y += h.y; acc.z += h.z; acc.w += h.w;
    }
    float inv = 1.f / (float)max(deg, 1);
    float4 pr = *(const float4*)(g_proj + (size_t)gw * 256 + 128 + lane * 4);
    float4 bb = *(const float4*)(bias + lane * 4);
    float4 o;
    o.x = fmaxf(fmaf(acc.x, inv, bb.x + pr.x), 0.f);
    o.y = fmaxf(fmaf(acc.y, inv, bb.y + pr.y), 0.f);
    o.z = fmaxf(fmaf(acc.z, inv, bb.z + pr.z), 0.f);
    o.w = fmaxf(fmaf(acc.w, inv, bb.w + pr.w), 0.f);
    float* out = osel ? g_ao : g_bo;
    *(float4*)(out + (size_t)gw * HID + lane * 4) = o;
}

// ---------------- crystal mean-pool + linear head ----------------
__global__ void pool_kernel(const int* __restrict__ crys,
                            const float* __restrict__ Wfc, const float* __restrict__ bfc,
                            float* __restrict__ out) {
    int b = blockIdx.x;
    int f = threadIdx.x;
    int start = crys[b * 2], end = crys[b * 2 + 1];
    const float* src = (f < 128) ? g_bo : g_ao;
    int fo = (f < 128) ? f : (f - 128);
    float s = 0.f;
    for (int a = start; a < end; a++) s += src[(size_t)a * HID + fo];
    __shared__ float pooled[256];
    pooled[f] = s / (float)(end - start);
    __syncthreads();
    int wid = f >> 5, lane = f & 31;
    if (wid < 2) {
        float d = 0.f;
        for (int i = lane; i < 256; i += 32) d += pooled[i] * Wfc[wid * 256 + i];
#pragma unroll
        for (int off = 16; off; off >>= 1) d += __shfl_down_sync(0xffffffffu, d, off);
        if (lane == 0) out[b * 2 + wid] = d + bfc[wid];
    }
}

// ---------------- host launcher ----------------
extern "C" void kernel_launch(void* const* d_in, const int* in_sizes, int n_in,
                              void* d_out, int out_size) {
    if (n_in < 19) return;

    int I_bond, I_angle, I_W1b, I_b1b, I_W1br, I_W1a, I_b1a, I_W1ar,
        I_W2b, I_b2b, I_W2br, I_W2a, I_b2a, I_W2ar, I_Wfc, I_bfc, I_nbr, I_crys;

    if (in_sizes[0] == 600000 && in_sizes[2] == 50000) {
        I_bond = 0; I_angle = 1; I_nbr = 3; I_crys = 4;
        I_W1b = 5;  I_b1b = 6;  I_W1br = 7;  I_W1a = 8;  I_b1a = 9;  I_W1ar = 10;
        I_W2b = 11; I_b2b = 12; I_W2br = 13; I_W2a = 14; I_b2a = 15; I_W2ar = 16;
        I_Wfc = 17; I_bfc = 18;
    } else if (in_sizes[0] == 600000) {
        I_bond = 0; I_angle = 1; I_W1b = 2; I_b1b = 3; I_W1br = 4;
        I_W1a = 5;  I_b1a = 6;  I_W1ar = 7; I_W2b = 8; I_b2b = 9; I_W2br = 10;
        I_W2a = 11; I_b2a = 12; I_W2ar = 13; I_Wfc = 14; I_bfc = 15;
        I_nbr = 17; I_crys = 18;
    } else {
        I_W1a = 0; I_W1ar = 1; I_W1b = 2; I_W1br = 3;
        I_W2a = 4; I_W2ar = 5; I_W2b = 6; I_W2br = 7; I_Wfc = 8;
        I_angle = 9; I_b1a = 10; I_b1b = 11; I_b2a = 12; I_b2b = 13; I_bfc = 14;
        I_bond = 15; I_crys = 16; I_nbr = 17;
    }

    const float* bond  = (const float*)d_in[I_bond];
    const float* angle = (const float*)d_in[I_angle];
    const int*   nbr   = (const int*)  d_in[I_nbr];
    const int*   crys  = (const int*)  d_in[I_crys];
    const float* W1b   = (const float*)d_in[I_W1b];
    const float* b1b   = (const float*)d_in[I_b1b];
    const float* W1br  = (const float*)d_in[I_W1br];
    const float* W1a   = (const float*)d_in[I_W1a];
    const float* b1a   = (const float*)d_in[I_b1a];
    const float* W1ar  = (const float*)d_in[I_W1ar];
    const float* W2b   = (const float*)d_in[I_W2b];
    const float* b2b   = (const float*)d_in[I_b2b];
    const float* W2br  = (const float*)d_in[I_W2br];
    const float* W2a   = (const float*)d_in[I_W2a];
    const float* b2a   = (const float*)d_in[I_b2a];
    const float* W2ar  = (const float*)d_in[I_W2ar];
    const float* Wfc   = (const float*)d_in[I_Wfc];
    const float* bfc   = (const float*)d_in[I_bfc];
    float* out = (float*)d_out;

    cudaFuncSetAttribute(hgemm_kernel<0, 40, 12>,  cudaFuncAttributeMaxDynamicSharedMemorySize, SM_TOTAL);
    cudaFuncSetAttribute(hgemm_kernel<0, 10, 144>, cudaFuncAttributeMaxDynamicSharedMemorySize, SM_TOTAL);
    cudaFuncSetAttribute(hgemm_kernel<1, 1, 1>,    cudaFuncAttributeMaxDynamicSharedMemorySize, SM_TOTAL);
    cudaFuncSetAttribute(hgemm_kernel<2, 1, 1>,    cudaFuncAttributeMaxDynamicSharedMemorySize, SM_TOTAL);

    const int gatherBlocks = (NA * 32 + 255) / 256;
    const dim3 ggemm(MPAD / 128, 2);

    zero_cnt_kernel<<<(NA + 255) / 256, 256>>>();
    count_kernel<<<(NEDGE + 255) / 256, 256>>>(nbr);

    // ---- layer 1, bond path: K=480 fused expansion (steps=40, nper=12) ----
    hgemm_kernel<0, 40, 12><<<ggemm, 256, SM_TOTAL>>>(
        W1b, W1br, bond, 480, 0.f, 8.f / 39.f, 25.f);
    gather_kernel<<<gatherBlocks, 256>>>(b1b, 0);

    // ---- layer 1, angle path: K=1440 fused expansion (steps=10, nper=144) ----
    hgemm_kernel<0, 10, 144><<<ggemm, 256, SM_TOTAL>>>(
        W1a, W1ar, angle, 1440, -1.f, 2.f / 9.f, 25.f);
    gather_kernel<<<gatherBlocks, 256>>>(b1a, 1);

    // ---- layer 2, bond path: K=128 ----
    hgemm_kernel<1, 1, 1><<<ggemm, 256, SM_TOTAL>>>(
        W2b, W2br, (const float*)0, 128, 0.f, 0.f, 0.f);
    gather_kernel<<<gatherBlocks, 256>>>(b2b, 0);

    // ---- layer 2, angle path: K=128 ----
    hgemm_kernel<2, 1, 1><<<ggemm, 256, SM_TOTAL>>>(
        W2a, W2ar, (const float*)0, 128, 0.f, 0.f, 0.f);
    gather_kernel<<<gatherBlocks, 256>>>(b2a, 1);

    // ---- pool + head ----
    pool_kernel<<<500, 256>>>(crys, Wfc, bfc, out);
}

// round 9
// speedup vs baseline: 2.8364x; 1.0348x over previous
#include <cuda_runtime.h>
#include <cuda_fp16.h>
#include <cstdint>
#include <mma.h>

using namespace nvcuda;

// ---------------- problem constants ----------------
#define NA     50000
#define MPAD   50048            // 391 * 128
#define NEIGH  12
#define NEDGE  (NA * NEIGH)
#define MAXDEG 64
#define HID    128

// ---------------- scratch (static device globals; no allocation) ----------------
__device__ float g_proj[(size_t)MPAD * 256];    // [proj_l | proj_r]
__device__ float g_bo  [(size_t)MPAD * HID];
__device__ float g_ao  [(size_t)MPAD * HID];
__device__ int   g_cnt [NA];
__device__ int   g_inc [(size_t)NA * MAXDEG];   // ELL incoming-edge source lists

// ---------------- graph inversion ----------------
__global__ void zero_cnt_kernel() {
    int i = blockIdx.x * blockDim.x + threadIdx.x;
    if (i < NA) g_cnt[i] = 0;
}
__global__ void count_kernel(const int* __restrict__ nbr) {
    int e = blockIdx.x * blockDim.x + threadIdx.x;
    if (e >= NEDGE) return;
    int d = nbr[e];
    int p = atomicAdd(&g_cnt[d], 1);
    if (p < MAXDEG) g_inc[(size_t)d * MAXDEG + p] = e / NEIGH;
}

// ---------------- full-range exp on FMA/ALU pipes (for x <= 0) ----------------
__device__ __forceinline__ float fast_exp(float x) {
    float t = x * 1.4426950408889634f;                 // x * log2(e)
    int   n = __float2int_rn(t);
    float r = (t - (float)n) * 0.6931471805599453f;    // r in [-0.347, 0.347]
    float p = fmaf(r, 1.f/720.f, 1.f/120.f);           // degree-6 Taylor of e^r
    p = fmaf(p, r, 1.f/24.f);
    p = fmaf(p, r, 1.f/6.f);
    p = fmaf(p, r, 0.5f);
    p = fmaf(p, r, 1.f);
    p = fmaf(p, r, 1.f);
    int e = n + 127;
    float s = __int_as_float(max(e, 0) << 23);         // 2^n, flush to 0 below 2^-127
    return p * s;
}

// ---------------- cp.async helpers ----------------
__device__ __forceinline__ uint32_t smem_u32(const void* p) {
    uint32_t a;
    asm("{ .reg .u64 t; cvta.to.shared.u64 t, %1; cvt.u32.u64 %0, t; }" : "=r"(a) : "l"(p));
    return a;
}
#define CP_ASYNC16(dst, src) \
    asm volatile("cp.async.cg.shared.global [%0], [%1], 16;" :: "r"(dst), "l"(src))
#define CP_COMMIT()  asm volatile("cp.async.commit_group;" ::: "memory")
#define CP_WAIT(n)   asm volatile("cp.async.wait_group %0;" :: "n"(n) : "memory")

// ---------------- fused fp16 wmma GEMM: g_proj[M, 0..256] = A[M,K] @ [Wl;Wr]^T ----------------
// ONE block computes the full N=256 tile (512 threads, 16 warps = 4m x 4n),
// so the Gaussian expansion (MODE 0) / A load (MODE 1,2) happens exactly once.
#define SMF_STRIDE 36                       // fp32 staging stride (floats)
#define SMF_A_TILE (128 * SMF_STRIDE)       // A staging tile (floats)
#define SMF_B_TILE (256 * SMF_STRIDE)       // B staging tile (floats): Wl(0-127) + Wr(128-255)
#define SMH_STRIDE 40                       // fp16 tile stride (halves)
#define SMH_A_TILE (128 * SMH_STRIDE)
#define SMH_B_TILE (256 * SMH_STRIDE)
// floats: FA0 FA1 FB0 FB1 then halves HA HB
#define SM_TOTAL ((2 * SMF_A_TILE + 2 * SMF_B_TILE) * 4 + (SMH_A_TILE + SMH_B_TILE) * 2)  // 141312 B

template<int MODE, int STEPS, int NPER>
__global__ void __launch_bounds__(512, 1)
hgemm_kernel(const float* __restrict__ Wl, const float* __restrict__ Wr,
             const float* __restrict__ fea, int K,
             float mu0, float dmu, float ig2)
{
    extern __shared__ float sm[];
    float* const FA[2] = { sm,                  sm + SMF_A_TILE };
    float* const FB[2] = { sm + 2 * SMF_A_TILE, sm + 2 * SMF_A_TILE + SMF_B_TILE };
    __half* const HA = (__half*)(sm + 2 * SMF_A_TILE + 2 * SMF_B_TILE);
    __half* const HB = HA + SMH_A_TILE;

    const float* __restrict__ A = (MODE == 1) ? g_bo : g_ao;   // load modes only

    const int tid = threadIdx.x;
    const size_t rowbase = (size_t)blockIdx.x * 128;
    const int T = K >> 5;

    // ---- loader addressing ----
    // B: 2 threads per row (256 rows), 16 floats each -> 4 x cp.async16
    const int brow = tid >> 1;
    const int bc16 = (tid & 1) << 4;
    const float* bSrc = (brow < 128 ? Wl + (size_t)brow * K
                                    : Wr + (size_t)(brow - 128) * K) + bc16;
    const uint32_t bDst0 = smem_u32(FB[0]) + (brow * SMF_STRIDE + bc16) * 4;
    // A: 4 threads per row (128 rows), 8 floats each -> 2 x cp.async16
    const int arow = tid >> 2;
    const int ac8  = (tid & 3) << 3;
    const float* aSrc = A + (rowbase + arow) * (size_t)K + ac8;
    const uint32_t aDst0 = smem_u32(FA[0]) + (arow * SMF_STRIDE + ac8) * 4;

    const uint32_t aBufStep = SMF_A_TILE * 4;
    const uint32_t bBufStep = SMF_B_TILE * 4;

    // prefetch chunk 0
#pragma unroll
    for (int i = 0; i < 4; i++) CP_ASYNC16(bDst0 + i * 16, bSrc + i * 4);
    if (MODE != 0) {
        CP_ASYNC16(aDst0,      aSrc);
        CP_ASYNC16(aDst0 + 16, aSrc + 4);
    }
    CP_COMMIT();

    const int warp = tid >> 5;
    const int wm = warp >> 2;           // 0..3 : 32-row slice
    const int wn = warp & 3;            // 0..3 : 64-col slice of N=256

    // generate/convert addressing for A: 4 threads per row, 8 values each
    const long grow = (long)rowbase + arow;
    const bool valid = grow < NA;
    const float* feaRow = (MODE == 0)
        ? fea + (size_t)(valid ? grow : 0) * NPER : (const float*)0;

    wmma::fragment<wmma::accumulator, 16, 16, 16, float> acc[2][4];
#pragma unroll
    for (int i = 0; i < 2; i++)
#pragma unroll
        for (int j = 0; j < 4; j++) wmma::fill_fragment(acc[i][j], 0.f);

    for (int t = 0; t < T; t++) {
        const int b = t & 1;
        if (t + 1 < T) {
            const int nb = (t + 1) & 1;
            const int k0 = (t + 1) << 5;
#pragma unroll
            for (int i = 0; i < 4; i++)
                CP_ASYNC16(bDst0 + nb * bBufStep + i * 16, bSrc + k0 + i * 4);
            if (MODE != 0) {
                CP_ASYNC16(aDst0 + nb * aBufStep,      aSrc + k0);
                CP_ASYNC16(aDst0 + nb * aBufStep + 16, aSrc + k0 + 4);
            }
            CP_COMMIT();
            CP_WAIT(1);
        } else {
            CP_WAIT(0);
        }
        __syncthreads();   // staging visible; all warps done reading HA/HB of t-1

        // ---- A tile: generate (MODE 0) or convert (MODE 1/2); 8 halves per thread ----
        if (MODE == 0) {
            const int kb = (t << 5) + ac8;
            __half2 hh[4];
#pragma unroll
            for (int j = 0; j < 8; j += 2) {
                int k0j = kb + j, k1j = kb + j + 1;
                int p0 = k0j / STEPS, s0 = k0j - p0 * STEPS;
                int p1 = k1j / STEPS, s1 = k1j - p1 * STEPS;
                float a0 = feaRow[p0], a1 = feaRow[p1];
                float d0 = a0 - fmaf((float)s0, dmu, mu0);
                float d1 = a1 - fmaf((float)s1, dmu, mu0);
                float v0 = fast_exp(-d0 * d0 * ig2);
                float v1 = fast_exp(-d1 * d1 * ig2);
                if (!valid) { v0 = 0.f; v1 = 0.f; }
                hh[j >> 1] = __floats2half2_rn(v0, v1);
            }
            *(uint4*)(HA + arow * SMH_STRIDE + ac8) = *(uint4*)&hh[0];
        } else {
            const float* fa = FA[b] + arow * SMF_STRIDE + ac8;
            __half2 ha[4];
#pragma unroll
            for (int i = 0; i < 2; i++) {
                float4 va = *(const float4*)(fa + i * 4);
                ha[i * 2 + 0] = __floats2half2_rn(va.x, va.y);
                ha[i * 2 + 1] = __floats2half2_rn(va.z, va.w);
            }
            *(uint4*)(HA + arow * SMH_STRIDE + ac8) = *(uint4*)&ha[0];
        }
        // ---- B tile convert: 16 halves per thread ----
        {
            const float* fb = FB[b] + brow * SMF_STRIDE + bc16;
            __half2 hb[8];
#pragma unroll
            for (int i = 0; i < 4; i++) {
                float4 vb = *(const float4*)(fb + i * 4);
                hb[i * 2 + 0] = __floats2half2_rn(vb.x, vb.y);
                hb[i * 2 + 1] = __floats2half2_rn(vb.z, vb.w);
            }
            __half* pb = HB + brow * SMH_STRIDE + bc16;
            *(uint4*)(pb)     = *(uint4*)&hb[0];
            *(uint4*)(pb + 8) = *(uint4*)&hb[4];
        }
        __syncthreads();   // fp16 tiles ready

#pragma unroll
        for (int ks = 0; ks < 2; ks++) {
            wmma::fragment<wmma::matrix_a, 16, 16, 16, __half, wmma::row_major> af[2];
            wmma::fragment<wmma::matrix_b, 16, 16, 16, __half, wmma::col_major> bf[4];
#pragma unroll
            for (int mt = 0; mt < 2; mt++)
                wmma::load_matrix_sync(af[mt], HA + (wm * 32 + mt * 16) * SMH_STRIDE + ks * 16, SMH_STRIDE);
#pragma unroll
            for (int nt = 0; nt < 4; nt++)
                wmma::load_matrix_sync(bf[nt], HB + (wn * 64 + nt * 16) * SMH_STRIDE + ks * 16, SMH_STRIDE);
#pragma unroll
            for (int mt = 0; mt < 2; mt++)
#pragma unroll
                for (int nt = 0; nt < 4; nt++)
                    wmma::mma_sync(acc[mt][nt], af[mt], bf[nt], acc[mt][nt]);
        }
    }

    const int colbase = wn * 64;
#pragma unroll
    for (int mt = 0; mt < 2; mt++) {
        const size_t row = rowbase + wm * 32 + mt * 16;
#pragma unroll
        for (int nt = 0; nt < 4; nt++)
            wmma::store_matrix_sync(g_proj + row * 256 + colbase + nt * 16,
                                    acc[mt][nt], 256, wmma::mem_row_major);
    }
}

// ---------------- mean-aggregate (gather) + bias + lin_r + ReLU ----------------
__global__ void gather_kernel(const float* __restrict__ bias, int osel) {
    int gw   = (blockIdx.x * blockDim.x + threadIdx.x) >> 5;
    int lane = threadIdx.x & 31;
    if (gw >= NA) return;

    int deg = g_cnt[gw];
    int dcl = min(deg, MAXDEG);
    int src_l = (lane < dcl) ? g_inc[(size_t)gw * MAXDEG + lane] : 0;

    float4 acc = make_float4(0.f, 0.f, 0.f, 0.f);
    for (int p = 0; p < dcl; p++) {
        int src = (p < 32) ? __shfl_sync(0xffffffffu, src_l, p)
                           : g_inc[(size_t)gw * MAXDEG + p];
        float4 h = *(const float4*)(g_proj + (size_t)src * 256 + lane * 4);
        acc.x += h.x; acc.y += h.y; acc.z += h.z; acc.w += h.w;
    }
    float inv = 1.f / (float)max(deg, 1);
    float4 pr = *(const float4*)(g_proj + (size_t)gw * 256 + 128 + lane * 4);
    float4 bb = *(const float4*)(bias + lane * 4);
    float4 o;
    o.x = fmaxf(fmaf(acc.x, inv, bb.x + pr.x), 0.f);
    o.y = fmaxf(fmaf(acc.y, inv, bb.y + pr.y), 0.f);
    o.z = fmaxf(fmaf(acc.z, inv, bb.z + pr.z), 0.f);
    o.w = fmaxf(fmaf(acc.w, inv, bb.w + pr.w), 0.f);
    float* out = osel ? g_ao : g_bo;
    *(float4*)(out + (size_t)gw * HID + lane * 4) = o;
}

// ---------------- crystal mean-pool + linear head ----------------
__global__ void pool_kernel(const int* __restrict__ crys,
                            const float* __restrict__ Wfc, const float* __restrict__ bfc,
                            float* __restrict__ out) {
    int b = blockIdx.x;
    int f = threadIdx.x;
    int start = crys[b * 2], end = crys[b * 2 + 1];
    const float* src = (f < 128) ? g_bo : g_ao;
    int fo = (f < 128) ? f : (f - 128);
    float s = 0.f;
    for (int a = start; a < end; a++) s += src[(size_t)a * HID + fo];
    __shared__ float pooled[256];
    pooled[f] = s / (float)(end - start);
    __syncthreads();
    int wid = f >> 5, lane = f & 31;
    if (wid < 2) {
        float d = 0.f;
        for (int i = lane; i < 256; i += 32) d += pooled[i] * Wfc[wid * 256 + i];
#pragma unroll
        for (int off = 16; off; off >>= 1) d += __shfl_down_sync(0xffffffffu, d, off);
        if (lane == 0) out[b * 2 + wid] = d + bfc[wid];
    }
}

// ---------------- host launcher ----------------
extern "C" void kernel_launch(void* const* d_in, const int* in_sizes, int n_in,
                              void* d_out, int out_size) {
    if (n_in < 19) return;

    int I_bond, I_angle, I_W1b, I_b1b, I_W1br, I_W1a, I_b1a, I_W1ar,
        I_W2b, I_b2b, I_W2br, I_W2a, I_b2a, I_W2ar, I_Wfc, I_bfc, I_nbr, I_crys;

    if (in_sizes[0] == 600000 && in_sizes[2] == 50000) {
        I_bond = 0; I_angle = 1; I_nbr = 3; I_crys = 4;
        I_W1b = 5;  I_b1b = 6;  I_W1br = 7;  I_W1a = 8;  I_b1a = 9;  I_W1ar = 10;
        I_W2b = 11; I_b2b = 12; I_W2br = 13; I_W2a = 14; I_b2a = 15; I_W2ar = 16;
        I_Wfc = 17; I_bfc = 18;
    } else if (in_sizes[0] == 600000) {
        I_bond = 0; I_angle = 1; I_W1b = 2; I_b1b = 3; I_W1br = 4;
        I_W1a = 5;  I_b1a = 6;  I_W1ar = 7; I_W2b = 8; I_b2b = 9; I_W2br = 10;
        I_W2a = 11; I_b2a = 12; I_W2ar = 13; I_Wfc = 14; I_bfc = 15;
        I_nbr = 17; I_crys = 18;
    } else {
        I_W1a = 0; I_W1ar = 1; I_W1b = 2; I_W1br = 3;
        I_W2a = 4; I_W2ar = 5; I_W2b = 6; I_W2br = 7; I_Wfc = 8;
        I_angle = 9; I_b1a = 10; I_b1b = 11; I_b2a = 12; I_b2b = 13; I_bfc = 14;
        I_bond = 15; I_crys = 16; I_nbr = 17;
    }

    const float* bond  = (const float*)d_in[I_bond];
    const float* angle = (const float*)d_in[I_angle];
    const int*   nbr   = (const int*)  d_in[I_nbr];
    const int*   crys  = (const int*)  d_in[I_crys];
    const float* W1b   = (const float*)d_in[I_W1b];
    const float* b1b   = (const float*)d_in[I_b1b];
    const float* W1br  = (const float*)d_in[I_W1br];
    const float* W1a   = (const float*)d_in[I_W1a];
    const float* b1a   = (const float*)d_in[I_b1a];
    const float* W1ar  = (const float*)d_in[I_W1ar];
    const float* W2b   = (const float*)d_in[I_W2b];
    const float* b2b   = (const float*)d_in[I_b2b];
    const float* W2br  = (const float*)d_in[I_W2br];
    const float* W2a   = (const float*)d_in[I_W2a];
    const float* b2a   = (const float*)d_in[I_b2a];
    const float* W2ar  = (const float*)d_in[I_W2ar];
    const float* Wfc   = (const float*)d_in[I_Wfc];
    const float* bfc   = (const float*)d_in[I_bfc];
    float* out = (float*)d_out;

    cudaFuncSetAttribute(hgemm_kernel<0, 40, 12>,  cudaFuncAttributeMaxDynamicSharedMemorySize, SM_TOTAL);
    cudaFuncSetAttribute(hgemm_kernel<0, 10, 144>, cudaFuncAttributeMaxDynamicSharedMemorySize, SM_TOTAL);
    cudaFuncSetAttribute(hgemm_kernel<1, 1, 1>,    cudaFuncAttributeMaxDynamicSharedMemorySize, SM_TOTAL);
    cudaFuncSetAttribute(hgemm_kernel<2, 1, 1>,    cudaFuncAttributeMaxDynamicSharedMemorySize, SM_TOTAL);

    const int gatherBlocks = (NA * 32 + 255) / 256;
    const int gemmBlocks = MPAD / 128;   // 391

    zero_cnt_kernel<<<(NA + 255) / 256, 256>>>();
    count_kernel<<<(NEDGE + 255) / 256, 256>>>(nbr);

    // ---- layer 1, bond path: K=480 fused expansion (steps=40, nper=12) ----
    hgemm_kernel<0, 40, 12><<<gemmBlocks, 512, SM_TOTAL>>>(
        W1b, W1br, bond, 480, 0.f, 8.f / 39.f, 25.f);
    gather_kernel<<<gatherBlocks, 256>>>(b1b, 0);

    // ---- layer 1, angle path: K=1440 fused expansion (steps=10, nper=144) ----
    hgemm_kernel<0, 10, 144><<<gemmBlocks, 512, SM_TOTAL>>>(
        W1a, W1ar, angle, 1440, -1.f, 2.f / 9.f, 25.f);
    gather_kernel<<<gatherBlocks, 256>>>(b1a, 1);

    // ---- layer 2, bond path: K=128 ----
    hgemm_kernel<1, 1, 1><<<gemmBlocks, 512, SM_TOTAL>>>(
        W2b, W2br, (const float*)0, 128, 0.f, 0.f, 0.f);
    gather_kernel<<<gatherBlocks, 256>>>(b2b, 0);

    // ---- layer 2, angle path: K=128 ----
    hgemm_kernel<2, 1, 1><<<gemmBlocks, 512, SM_TOTAL>>>(
        W2a, W2ar, (const float*)0, 128, 0.f, 0.f, 0.f);
    gather_kernel<<<gatherBlocks, 256>>>(b2a, 1);

    // ---- pool + head ----
    pool_kernel<<<500, 256>>>(crys, Wfc, bfc, out);
}

// round 10
// speedup vs baseline: 3.0731x; 1.0835x over previous
#include <cuda_runtime.h>
#include <cuda_fp16.h>
#include <cstdint>
#include <mma.h>

using namespace nvcuda;

// ---------------- problem constants ----------------
#define NA     50000
#define MPAD   50048            // 391 * 128
#define NEIGH  12
#define NEDGE  (NA * NEIGH)
#define MAXDEG 64
#define HID    128

// ---------------- scratch (static device globals; no allocation) ----------------
__device__ float g_proj[(size_t)MPAD * 256];    // [proj_l | proj_r]
__device__ float g_bo  [(size_t)MPAD * HID];
__device__ float g_ao  [(size_t)MPAD * HID];
__device__ int   g_cnt [NA];
__device__ int   g_inc [(size_t)NA * MAXDEG];   // ELL incoming-edge source lists

// ---------------- graph inversion ----------------
__global__ void zero_cnt_kernel() {
    int i = blockIdx.x * blockDim.x + threadIdx.x;
    if (i < NA) g_cnt[i] = 0;
}
__global__ void count_kernel(const int* __restrict__ nbr) {
    int e = blockIdx.x * blockDim.x + threadIdx.x;
    if (e >= NEDGE) return;
    int d = nbr[e];
    int p = atomicAdd(&g_cnt[d], 1);
    if (p < MAXDEG) g_inc[(size_t)d * MAXDEG + p] = e / NEIGH;
}

// ---------------- full-range exp on FMA/ALU pipes (for x <= 0) ----------------
__device__ __forceinline__ float fast_exp(float x) {
    float t = x * 1.4426950408889634f;                 // x * log2(e)
    int   n = __float2int_rn(t);
    float r = (t - (float)n) * 0.6931471805599453f;    // r in [-0.347, 0.347]
    float p = fmaf(r, 1.f/720.f, 1.f/120.f);           // degree-6 Taylor of e^r
    p = fmaf(p, r, 1.f/24.f);
    p = fmaf(p, r, 1.f/6.f);
    p = fmaf(p, r, 0.5f);
    p = fmaf(p, r, 1.f);
    p = fmaf(p, r, 1.f);
    int e = n + 127;
    float s = __int_as_float(max(e, 0) << 23);         // 2^n, flush to 0 below 2^-127
    return p * s;
}

// ---------------- cp.async helpers ----------------
__device__ __forceinline__ uint32_t smem_u32(const void* p) {
    uint32_t a;
    asm("{ .reg .u64 t; cvta.to.shared.u64 t, %1; cvt.u32.u64 %0, t; }" : "=r"(a) : "l"(p));
    return a;
}
#define CP_ASYNC16(dst, src) \
    asm volatile("cp.async.cg.shared.global [%0], [%1], 16;" :: "r"(dst), "l"(src))
#define CP_COMMIT()  asm volatile("cp.async.commit_group;" ::: "memory")
#define CP_WAIT(n)   asm volatile("cp.async.wait_group %0;" :: "n"(n) : "memory")

// ---------------- fused fp16 wmma GEMM: g_proj[M, 0..256] = A[M,K] @ [Wl;Wr]^T ----------------
// 512 threads, 16 warps = 4m x 4n. Single __syncthreads per K-chunk:
// fp16 tiles double-buffered; each thread converts exactly the staging words it loaded,
// so staging needs only cp.async.wait_group (same-thread ordering).
#define SMF_STRIDE 36                       // fp32 staging stride (floats)
#define SMF_A_TILE (128 * SMF_STRIDE)
#define SMF_B_TILE (256 * SMF_STRIDE)
#define SMH_STRIDE 40                       // fp16 tile stride (halves)
#define SMH_A_TILE (128 * SMH_STRIDE)
#define SMH_B_TILE (256 * SMH_STRIDE)
// floats: FA0 FA1 FB0 FB1 ; halves: HA0 HA1 HB0 HB1
#define SM_TOTAL ((2 * SMF_A_TILE + 2 * SMF_B_TILE) * 4 + 2 * (SMH_A_TILE + SMH_B_TILE) * 2)  // 172032 B

template<int MODE, int STEPS, int NPER>
__global__ void __launch_bounds__(512, 1)
hgemm_kernel(const float* __restrict__ Wl, const float* __restrict__ Wr,
             const float* __restrict__ fea, int K,
             float mu0, float dmu, float ig2)
{
    extern __shared__ float sm[];
    float*  const FAp = sm;                                   // 2 x A staging
    float*  const FBp = sm + 2 * SMF_A_TILE;                  // 2 x B staging
    __half* const HAp = (__half*)(sm + 2 * SMF_A_TILE + 2 * SMF_B_TILE);
    __half* const HBp = HAp + 2 * SMH_A_TILE;

    const float* __restrict__ A = (MODE == 1) ? g_bo : g_ao;   // load modes only

    const int tid = threadIdx.x;
    const size_t rowbase = (size_t)blockIdx.x * 128;
    const int T = K >> 5;

    // ---- loader addressing (each thread later converts exactly what it loads) ----
    const int brow = tid >> 1;
    const int bc16 = (tid & 1) << 4;
    const float* bSrc = (brow < 128 ? Wl + (size_t)brow * K
                                    : Wr + (size_t)(brow - 128) * K) + bc16;
    const uint32_t bDst0 = smem_u32(FBp) + (brow * SMF_STRIDE + bc16) * 4;
    const int arow = tid >> 2;
    const int ac8  = (tid & 3) << 3;
    const float* aSrc = A + (rowbase + arow) * (size_t)K + ac8;
    const uint32_t aDst0 = smem_u32(FAp) + (arow * SMF_STRIDE + ac8) * 4;
    const uint32_t aBufStep = SMF_A_TILE * 4;
    const uint32_t bBufStep = SMF_B_TILE * 4;

    const int warp = tid >> 5;
    const int wm = warp >> 2;           // 0..3 : 32-row slice
    const int wn = warp & 3;            // 0..3 : 64-col slice of N=256

    const long grow = (long)rowbase + arow;
    const bool valid = grow < NA;
    const float* feaRow = (MODE == 0)
        ? fea + (size_t)(valid ? grow : 0) * NPER : (const float*)0;

    wmma::fragment<wmma::accumulator, 16, 16, 16, float> acc[2][4];
#pragma unroll
    for (int i = 0; i < 2; i++)
#pragma unroll
        for (int j = 0; j < 4; j++) wmma::fill_fragment(acc[i][j], 0.f);

    // ---- pipeline stage helpers ----
    auto stage_async = [&](int tc) {                 // cp.async chunk tc -> staging[tc&1]
        const int k0 = tc << 5;
        const uint32_t sb = (uint32_t)(tc & 1);
#pragma unroll
        for (int i = 0; i < 4; i++)
            CP_ASYNC16(bDst0 + sb * bBufStep + i * 16, bSrc + k0 + i * 4);
        if (MODE != 0) {
            CP_ASYNC16(aDst0 + sb * aBufStep,      aSrc + k0);
            CP_ASYNC16(aDst0 + sb * aBufStep + 16, aSrc + k0 + 4);
        }
        CP_COMMIT();
    };

    auto convert_chunk = [&](int tc) {               // staging[tc&1] / gen -> H[tc&1]
        const int sb = tc & 1;
        __half* HA_ = HAp + sb * SMH_A_TILE;
        __half* HB_ = HBp + sb * SMH_B_TILE;
        if (MODE == 0) {
            const int kb = (tc << 5) + ac8;
            __half2 hh[4];
#pragma unroll
            for (int j = 0; j < 8; j += 2) {
                int k0j = kb + j, k1j = kb + j + 1;
                int p0 = k0j / STEPS, s0 = k0j - p0 * STEPS;
                int p1 = k1j / STEPS, s1 = k1j - p1 * STEPS;
                float a0 = feaRow[p0], a1 = feaRow[p1];
                float d0 = a0 - fmaf((float)s0, dmu, mu0);
                float d1 = a1 - fmaf((float)s1, dmu, mu0);
                float v0 = fast_exp(-d0 * d0 * ig2);
                float v1 = fast_exp(-d1 * d1 * ig2);
                if (!valid) { v0 = 0.f; v1 = 0.f; }
                hh[j >> 1] = __floats2half2_rn(v0, v1);
            }
            *(uint4*)(HA_ + arow * SMH_STRIDE + ac8) = *(uint4*)&hh[0];
        } else {
            const float* fa = FAp + sb * SMF_A_TILE + arow * SMF_STRIDE + ac8;
            __half2 ha[4];
#pragma unroll
            for (int i = 0; i < 2; i++) {
                float4 va = *(const float4*)(fa + i * 4);
                ha[i * 2 + 0] = __floats2half2_rn(va.x, va.y);
                ha[i * 2 + 1] = __floats2half2_rn(va.z, va.w);
            }
            *(uint4*)(HA_ + arow * SMH_STRIDE + ac8) = *(uint4*)&ha[0];
        }
        {
            const float* fb = FBp + sb * SMF_B_TILE + brow * SMF_STRIDE + bc16;
            __half2 hb[8];
#pragma unroll
            for (int i = 0; i < 4; i++) {
                float4 vb = *(const float4*)(fb + i * 4);
                hb[i * 2 + 0] = __floats2half2_rn(vb.x, vb.y);
                hb[i * 2 + 1] = __floats2half2_rn(vb.z, vb.w);
            }
            __half* pb = HB_ + brow * SMH_STRIDE + bc16;
            *(uint4*)(pb)     = *(uint4*)&hb[0];
            *(uint4*)(pb + 8) = *(uint4*)&hb[4];
        }
    };

    auto mma_chunk = [&](int sb) {
        __half* HA_ = HAp + sb * SMH_A_TILE;
        __half* HB_ = HBp + sb * SMH_B_TILE;
#pragma unroll
        for (int ks = 0; ks < 2; ks++) {
            wmma::fragment<wmma::matrix_a, 16, 16, 16, __half, wmma::row_major> af[2];
            wmma::fragment<wmma::matrix_b, 16, 16, 16, __half, wmma::col_major> bf[4];
#pragma unroll
            for (int mt = 0; mt < 2; mt++)
                wmma::load_matrix_sync(af[mt], HA_ + (wm * 32 + mt * 16) * SMH_STRIDE + ks * 16, SMH_STRIDE);
#pragma unroll
            for (int nt = 0; nt < 4; nt++)
                wmma::load_matrix_sync(bf[nt], HB_ + (wn * 64 + nt * 16) * SMH_STRIDE + ks * 16, SMH_STRIDE);
#pragma unroll
            for (int mt = 0; mt < 2; mt++)
#pragma unroll
                for (int nt = 0; nt < 4; nt++)
                    wmma::mma_sync(acc[mt][nt], af[mt], bf[nt], acc[mt][nt]);
        }
    };

    // ---- prologue: chunks 0 and 1 in flight; convert chunk 0 ----
    stage_async(0);
    if (T > 1) { stage_async(1); CP_WAIT(1); }
    else       { CP_WAIT(0); }
    convert_chunk(0);

    // ---- mainloop: one barrier per chunk; MMA(t) issued before convert(t+1) ----
    for (int t = 0; t < T; t++) {
        __syncthreads();                    // H[t&1] published by all threads
        mma_chunk(t & 1);
        if (t + 2 < T) stage_async(t + 2);
        if (t + 1 < T) {
            if (t + 2 < T) { CP_WAIT(1); } else { CP_WAIT(0); }
            convert_chunk(t + 1);
        }
    }

    const int colbase = wn * 64;
#pragma unroll
    for (int mt = 0; mt < 2; mt++) {
        const size_t row = rowbase + wm * 32 + mt * 16;
#pragma unroll
        for (int nt = 0; nt < 4; nt++)
            wmma::store_matrix_sync(g_proj + row * 256 + colbase + nt * 16,
                                    acc[mt][nt], 256, wmma::mem_row_major);
    }
}

// ---------------- mean-aggregate (gather) + bias + lin_r + ReLU ----------------
__global__ void gather_kernel(const float* __restrict__ bias, int osel) {
    int gw   = (blockIdx.x * blockDim.x + threadIdx.x) >> 5;
    int lane = threadIdx.x & 31;
    if (gw >= NA) return;

    int deg = g_cnt[gw];
    int dcl = min(deg, MAXDEG);
    int src_l = (lane < dcl) ? g_inc[(size_t)gw * MAXDEG + lane] : 0;

    float4 acc = make_float4(0.f, 0.f, 0.f, 0.f);
    for (int p = 0; p < dcl; p++) {
        int src = (p < 32) ? __shfl_sync(0xffffffffu, src_l, p)
                           : g_inc[(size_t)gw * MAXDEG + p];
        float4 h = *(const float4*)(g_proj + (size_t)src * 256 + lane * 4);
        acc.x += h.x; acc.y += h.y; acc.z += h.z; acc.w += h.w;
    }
    float inv = 1.f / (float)max(deg, 1);
    float4 pr = *(const float4*)(g_proj + (size_t)gw * 256 + 128 + lane * 4);
    float4 bb = *(const float4*)(bias + lane * 4);
    float4 o;
    o.x = fmaxf(fmaf(acc.x, inv, bb.x + pr.x), 0.f);
    o.y = fmaxf(fmaf(acc.y, inv, bb.y + pr.y), 0.f);
    o.z = fmaxf(fmaf(acc.z, inv, bb.z + pr.z), 0.f);
    o.w = fmaxf(fmaf(acc.w, inv, bb.w + pr.w), 0.f);
    float* out = osel ? g_ao : g_bo;
    *(float4*)(out + (size_t)gw * HID + lane * 4) = o;
}

// ---------------- crystal mean-pool + linear head ----------------
__global__ void pool_kernel(const int* __restrict__ crys,
                            const float* __restrict__ Wfc, const float* __restrict__ bfc,
                            float* __restrict__ out) {
    int b = blockIdx.x;
    int f = threadIdx.x;
    int start = crys[b * 2], end = crys[b * 2 + 1];
    const float* src = (f < 128) ? g_bo : g_ao;
    int fo = (f < 128) ? f : (f - 128);
    float s = 0.f;
    for (int a = start; a < end; a++) s += src[(size_t)a * HID + fo];
    __shared__ float pooled[256];
    pooled[f] = s / (float)(end - start);
    __syncthreads();
    int wid = f >> 5, lane = f & 31;
    if (wid < 2) {
        float d = 0.f;
        for (int i = lane; i < 256; i += 32) d += pooled[i] * Wfc[wid * 256 + i];
#pragma unroll
        for (int off = 16; off; off >>= 1) d += __shfl_down_sync(0xffffffffu, d, off);
        if (lane == 0) out[b * 2 + wid] = d + bfc[wid];
    }
}

// ---------------- host launcher ----------------
extern "C" void kernel_launch(void* const* d_in, const int* in_sizes, int n_in,
                              void* d_out, int out_size) {
    if (n_in < 19) return;

    int I_bond, I_angle, I_W1b, I_b1b, I_W1br, I_W1a, I_b1a, I_W1ar,
        I_W2b, I_b2b, I_W2br, I_W2a, I_b2a, I_W2ar, I_Wfc, I_bfc, I_nbr, I_crys;

    if (in_sizes[0] == 600000 && in_sizes[2] == 50000) {
        I_bond = 0; I_angle = 1; I_nbr = 3; I_crys = 4;
        I_W1b = 5;  I_b1b = 6;  I_W1br = 7;  I_W1a = 8;  I_b1a = 9;  I_W1ar = 10;
        I_W2b = 11; I_b2b = 12; I_W2br = 13; I_W2a = 14; I_b2a = 15; I_W2ar = 16;
        I_Wfc = 17; I_bfc = 18;
    } else if (in_sizes[0] == 600000) {
        I_bond = 0; I_angle = 1; I_W1b = 2; I_b1b = 3; I_W1br = 4;
        I_W1a = 5;  I_b1a = 6;  I_W1ar = 7; I_W2b = 8; I_b2b = 9; I_W2br = 10;
        I_W2a = 11; I_b2a = 12; I_W2ar = 13; I_Wfc = 14; I_bfc = 15;
        I_nbr = 17; I_crys = 18;
    } else {
        I_W1a = 0; I_W1ar = 1; I_W1b = 2; I_W1br = 3;
        I_W2a = 4; I_W2ar = 5; I_W2b = 6; I_W2br = 7; I_Wfc = 8;
        I_angle = 9; I_b1a = 10; I_b1b = 11; I_b2a = 12; I_b2b = 13; I_bfc = 14;
        I_bond = 15; I_crys = 16; I_nbr = 17;
    }

    const float* bond  = (const float*)d_in[I_bond];
    const float* angle = (const float*)d_in[I_angle];
    const int*   nbr   = (const int*)  d_in[I_nbr];
    const int*   crys  = (const int*)  d_in[I_crys];
    const float* W1b   = (const float*)d_in[I_W1b];
    const float* b1b   = (const float*)d_in[I_b1b];
    const float* W1br  = (const float*)d_in[I_W1br];
    const float* W1a   = (const float*)d_in[I_W1a];
    const float* b1a   = (const float*)d_in[I_b1a];
    const float* W1ar  = (const float*)d_in[I_W1ar];
    const float* W2b   = (const float*)d_in[I_W2b];
    const float* b2b   = (const float*)d_in[I_b2b];
    const float* W2br  = (const float*)d_in[I_W2br];
    const float* W2a   = (const float*)d_in[I_W2a];
    const float* b2a   = (const float*)d_in[I_b2a];
    const float* W2ar  = (const float*)d_in[I_W2ar];
    const float* Wfc   = (const float*)d_in[I_Wfc];
    const float* bfc   = (const float*)d_in[I_bfc];
    float* out = (float*)d_out;

    cudaFuncSetAttribute(hgemm_kernel<0, 40, 12>,  cudaFuncAttributeMaxDynamicSharedMemorySize, SM_TOTAL);
    cudaFuncSetAttribute(hgemm_kernel<0, 10, 144>, cudaFuncAttributeMaxDynamicSharedMemorySize, SM_TOTAL);
    cudaFuncSetAttribute(hgemm_kernel<1, 1, 1>,    cudaFuncAttributeMaxDynamicSharedMemorySize, SM_TOTAL);
    cudaFuncSetAttribute(hgemm_kernel<2, 1, 1>,    cudaFuncAttributeMaxDynamicSharedMemorySize, SM_TOTAL);

    const int gatherBlocks = (NA * 32 + 255) / 256;
    const int gemmBlocks = MPAD / 128;   // 391

    zero_cnt_kernel<<<(NA + 255) / 256, 256>>>();
    count_kernel<<<(NEDGE + 255) / 256, 256>>>(nbr);

    // ---- layer 1, bond path: K=480 fused expansion (steps=40, nper=12) ----
    hgemm_kernel<0, 40, 12><<<gemmBlocks, 512, SM_TOTAL>>>(
        W1b, W1br, bond, 480, 0.f, 8.f / 39.f, 25.f);
    gather_kernel<<<gatherBlocks, 256>>>(b1b, 0);

    // ---- layer 1, angle path: K=1440 fused expansion (steps=10, nper=144) ----
    hgemm_kernel<0, 10, 144><<<gemmBlocks, 512, SM_TOTAL>>>(
        W1a, W1ar, angle, 1440, -1.f, 2.f / 9.f, 25.f);
    gather_kernel<<<gatherBlocks, 256>>>(b1a, 1);

    // ---- layer 2, bond path: K=128 ----
    hgemm_kernel<1, 1, 1><<<gemmBlocks, 512, SM_TOTAL>>>(
        W2b, W2br, (const float*)0, 128, 0.f, 0.f, 0.f);
    gather_kernel<<<gatherBlocks, 256>>>(b2b, 0);

    // ---- layer 2, angle path: K=128 ----
    hgemm_kernel<2, 1, 1><<<gemmBlocks, 512, SM_TOTAL>>>(
        W2a, W2ar, (const float*)0, 128, 0.f, 0.f, 0.f);
    gather_kernel<<<gatherBlocks, 256>>>(b2a, 1);

    // ---- pool + head ----
    pool_kernel<<<500, 256>>>(crys, Wfc, bfc, out);
}